// round 1
// baseline (speedup 1.0000x reference)
#include <cuda_runtime.h>
#include <cstdint>
#include <cstdio>

#define NP 2048
#define NC 64
#define CDIM 128
#define DDIM 64
#define NCC (NC*CDIM)              /* 8192 */
#define TOT ((size_t)NP*NCC)       /* 16777216 */
#define P_TOPP 0.9f
#define LN_EPS 1e-5f

// ---------------- scratch (device globals; allowed) ----------------
__device__ float g_Rf[(size_t)NP*NP];
__device__ float g_attn[(size_t)NP*NP];
__device__ float g_rowinv[NP];
__device__ float g_pooled[NP*CDIM];
__device__ float g_e1[NP*DDIM];
__device__ float g_e3[NP*DDIM];
__device__ float g_fm[NP*DDIM];
__device__ float g_thr[NP];
__device__ float g_scl[NP];
__device__ float g_Xf1[TOT];
__device__ float g_Xa1[TOT];
__device__ float g_Xf2[TOT];
__device__ float g_Xa2[TOT];
__device__ float g_res[TOT];

// ---------------- prior row-normalization ----------------
__global__ void k_rowsum(const float* __restrict__ prior) {
    __shared__ float red[256];
    int row = blockIdx.x, t = threadIdx.x;
    const float* p = prior + (size_t)row * NP;
    float s = 0.f;
    for (int j = t; j < NP; j += 256) s += p[j];
    red[t] = s; __syncthreads();
    for (int o = 128; o; o >>= 1) { if (t < o) red[t] += red[t + o]; __syncthreads(); }
    if (t == 0) g_rowinv[row] = 1.0f / fmaxf(red[0], 1e-12f);
}

__global__ void k_scaleRf(const float* __restrict__ prior) {
    size_t idx = (size_t)blockIdx.x * blockDim.x + threadIdx.x;
    size_t stride = (size_t)gridDim.x * blockDim.x;
    for (size_t i = idx; i < (size_t)NP * NP; i += stride)
        g_Rf[i] = prior[i] * g_rowinv[i >> 11];
}

// ---------------- mean pool over protein axis ----------------
__global__ void k_pool(const float* __restrict__ X) {
    int i = blockIdx.x, c = threadIdx.x;  // 128 threads
    const float* p = X + (size_t)i * NCC + c;
    float s = 0.f;
#pragma unroll
    for (int k = 0; k < NC; k++) s += p[k * CDIM];
    g_pooled[i * CDIM + c] = s * (1.0f / NC);
}

// ---------------- small projections ----------------
__global__ void k_e1e3(const float* __restrict__ W1, const float* __restrict__ W3) {
    int i = blockIdx.x, d = threadIdx.x;  // 64 threads
    __shared__ float p[CDIM];
    p[d] = g_pooled[i * CDIM + d];
    p[d + 64] = g_pooled[i * CDIM + d + 64];
    __syncthreads();
    float s1 = 0.f, s3 = 0.f;
#pragma unroll 4
    for (int c = 0; c < CDIM; c++) {
        float pc = p[c];
        s1 += pc * W1[d * CDIM + c];
        s3 += pc * W3[d * CDIM + c];
    }
    g_e1[i * DDIM + d] = s1;
    g_e3[i * DDIM + d] = s3;
}

__global__ void k_f(const float* __restrict__ W2) {
    int i = blockIdx.x, d = threadIdx.x;  // 64 threads
    __shared__ float e[DDIM];
    e[d] = g_e1[i * DDIM + d];
    __syncthreads();
    float s = 0.f;
#pragma unroll 4
    for (int k = 0; k < DDIM; k++) s += e[k] * W2[d * DDIM + k];
    g_fm[i * DDIM + d] = s;
}

// logits[i,n] = sum_k f[i,k]*e3[n,k]  (TAU = 1)
__global__ __launch_bounds__(256) void k_logits() {
    __shared__ float Fs[64][65];
    __shared__ float Es[64][65];
    int bm = blockIdx.y * 64, bn = blockIdx.x * 64;
    int t = threadIdx.x;
    for (int idx = t; idx < 64 * 64; idx += 256) {
        int r = idx >> 6, c = idx & 63;
        Fs[r][c] = g_fm[(bm + r) * 64 + c];
        Es[r][c] = g_e3[(bn + r) * 64 + c];
    }
    __syncthreads();
    int tx = t & 15, ty = t >> 4;
    float acc[4][4] = {};
    for (int k = 0; k < 64; k++) {
        float a[4], b[4];
#pragma unroll
        for (int r = 0; r < 4; r++) { a[r] = Fs[ty * 4 + r][k]; b[r] = Es[tx * 4 + r][k]; }
#pragma unroll
        for (int i = 0; i < 4; i++)
#pragma unroll
            for (int j = 0; j < 4; j++) acc[i][j] += a[i] * b[j];
    }
#pragma unroll
    for (int i = 0; i < 4; i++)
#pragma unroll
        for (int j = 0; j < 4; j++)
            g_attn[(size_t)(bm + ty * 4 + i) * NP + bn + tx * 4 + j] = acc[i][j];
}

// ---------------- row softmax (in place on g_attn) ----------------
__global__ void k_softmax() {
    int row = blockIdx.x, t = threadIdx.x;  // 256 threads
    float* a = g_attn + (size_t)row * NP;
    __shared__ float red[256];
    float m = -1e30f;
    for (int j = t; j < NP; j += 256) m = fmaxf(m, a[j]);
    red[t] = m; __syncthreads();
    for (int o = 128; o; o >>= 1) { if (t < o) red[t] = fmaxf(red[t], red[t + o]); __syncthreads(); }
    m = red[0];
    __syncthreads();
    float s = 0.f;
    for (int j = t; j < NP; j += 256) { float e = expf(a[j] - m); a[j] = e; s += e; }
    red[t] = s; __syncthreads();
    for (int o = 128; o; o >>= 1) { if (t < o) red[t] += red[t + o]; __syncthreads(); }
    float inv = 1.0f / red[0];
    for (int j = t; j < NP; j += 256) a[j] *= inv;
}

// ---------------- top-p: per-row bitonic sort + scan -> thr, 1/masked_sum ----------------
__global__ __launch_bounds__(1024) void k_topp() {
    __shared__ float s[2048];
    __shared__ float cs[2048];
    __shared__ int kmax;
    int row = blockIdx.x, t = threadIdx.x;
    const float* a = g_attn + (size_t)row * NP;
    s[t] = a[t]; s[t + 1024] = a[t + 1024];
    __syncthreads();
    // bitonic sort, descending
    for (int k = 2; k <= 2048; k <<= 1) {
        for (int j = k >> 1; j > 0; j >>= 1) {
#pragma unroll
            for (int u = 0; u < 2; u++) {
                int i = t + u * 1024;
                int ixj = i ^ j;
                if (ixj > i) {
                    float xi = s[i], xj = s[ixj];
                    bool descBlk = ((i & k) == 0);
                    bool sw = descBlk ? (xi < xj) : (xi > xj);
                    if (sw) { s[i] = xj; s[ixj] = xi; }
                }
            }
            __syncthreads();
        }
    }
    // inclusive scan (Hillis-Steele)
    cs[t] = s[t]; cs[t + 1024] = s[t + 1024];
    __syncthreads();
    for (int off = 1; off < 2048; off <<= 1) {
        float v0 = (t >= off) ? cs[t - off] : 0.f;
        int t1 = t + 1024;
        float v1 = (t1 >= off) ? cs[t1 - off] : 0.f;
        __syncthreads();
        cs[t] += v0; cs[t1] += v1;
        __syncthreads();
    }
    if (t == 0) kmax = 0;
    __syncthreads();
    if (cs[t] - s[t] < P_TOPP) atomicMax(&kmax, t);
    if (cs[t + 1024] - s[t + 1024] < P_TOPP) atomicMax(&kmax, t + 1024);
    __syncthreads();
    float thr = s[kmax];
    float part = (s[t] >= thr ? s[t] : 0.f) + (s[t + 1024] >= thr ? s[t + 1024] : 0.f);
    __syncthreads();
    cs[t] = part; __syncthreads();
    for (int o = 512; o; o >>= 1) { if (t < o) cs[t] += cs[t + o]; __syncthreads(); }
    if (t == 0) {
        g_thr[row] = thr;
        g_scl[row] = 1.0f / fmaxf(cs[0], 1e-12f);
    }
}

// sparsify + renormalize attn in place
__global__ void k_mask() {
    size_t idx = (size_t)blockIdx.x * blockDim.x + threadIdx.x;
    size_t stride = (size_t)gridDim.x * blockDim.x;
    for (size_t i = idx; i < (size_t)NP * NP; i += stride) {
        int r = (int)(i >> 11);
        float v = g_attn[i];
        g_attn[i] = (v >= g_thr[r]) ? v * g_scl[r] : 0.0f;
    }
}

// ---------------- big SGEMM: C = A(MxK) * B(KxN), fp32, 128x128x16, double-buffered ----------------
__global__ __launch_bounds__(256) void k_sgemm(const float* __restrict__ A, const float* __restrict__ B,
                                               float* __restrict__ C, int M, int N, int K) {
    __shared__ float As[2][16][132];
    __shared__ float Bs[2][16][128];
    int t = threadIdx.x;
    int bm = blockIdx.y << 7;
    int bn = blockIdx.x << 7;
    int a_r0 = t >> 2, a_c0 = (t & 3) << 2;
    int a_r1 = a_r0 + 64;
    int b_r0 = t >> 5, b_c0 = (t & 31) << 2;
    int b_r1 = b_r0 + 8;
    int tx = t & 15, ty = t >> 4;
    int cm = ty << 3, cn = tx << 3;
    float acc[8][8] = {};
    float4 pa0, pa1, pb0, pb1;

    pa0 = *(const float4*)&A[(size_t)(bm + a_r0) * K + a_c0];
    pa1 = *(const float4*)&A[(size_t)(bm + a_r1) * K + a_c0];
    pb0 = *(const float4*)&B[(size_t)b_r0 * N + bn + b_c0];
    pb1 = *(const float4*)&B[(size_t)b_r1 * N + bn + b_c0];
    As[0][a_c0 + 0][a_r0] = pa0.x; As[0][a_c0 + 1][a_r0] = pa0.y;
    As[0][a_c0 + 2][a_r0] = pa0.z; As[0][a_c0 + 3][a_r0] = pa0.w;
    As[0][a_c0 + 0][a_r1] = pa1.x; As[0][a_c0 + 1][a_r1] = pa1.y;
    As[0][a_c0 + 2][a_r1] = pa1.z; As[0][a_c0 + 3][a_r1] = pa1.w;
    *(float4*)&Bs[0][b_r0][b_c0] = pb0;
    *(float4*)&Bs[0][b_r1][b_c0] = pb1;
    __syncthreads();

    int nt = K >> 4;
    for (int tile = 0; tile < nt; tile++) {
        int cur = tile & 1;
        if (tile + 1 < nt) {
            int k0 = (tile + 1) << 4;
            pa0 = *(const float4*)&A[(size_t)(bm + a_r0) * K + k0 + a_c0];
            pa1 = *(const float4*)&A[(size_t)(bm + a_r1) * K + k0 + a_c0];
            pb0 = *(const float4*)&B[(size_t)(k0 + b_r0) * N + bn + b_c0];
            pb1 = *(const float4*)&B[(size_t)(k0 + b_r1) * N + bn + b_c0];
        }
#pragma unroll
        for (int k = 0; k < 16; k++) {
            float ar[8], br[8];
            *(float4*)&ar[0] = *(const float4*)&As[cur][k][cm];
            *(float4*)&ar[4] = *(const float4*)&As[cur][k][cm + 4];
            *(float4*)&br[0] = *(const float4*)&Bs[cur][k][cn];
            *(float4*)&br[4] = *(const float4*)&Bs[cur][k][cn + 4];
#pragma unroll
            for (int i = 0; i < 8; i++)
#pragma unroll
                for (int j = 0; j < 8; j++) acc[i][j] = fmaf(ar[i], br[j], acc[i][j]);
        }
        if (tile + 1 < nt) {
            int nxt = cur ^ 1;
            As[nxt][a_c0 + 0][a_r0] = pa0.x; As[nxt][a_c0 + 1][a_r0] = pa0.y;
            As[nxt][a_c0 + 2][a_r0] = pa0.z; As[nxt][a_c0 + 3][a_r0] = pa0.w;
            As[nxt][a_c0 + 0][a_r1] = pa1.x; As[nxt][a_c0 + 1][a_r1] = pa1.y;
            As[nxt][a_c0 + 2][a_r1] = pa1.z; As[nxt][a_c0 + 3][a_r1] = pa1.w;
            *(float4*)&Bs[nxt][b_r0][b_c0] = pb0;
            *(float4*)&Bs[nxt][b_r1][b_c0] = pb1;
            __syncthreads();
        }
    }
#pragma unroll
    for (int i = 0; i < 8; i++) {
        size_t off = (size_t)(bm + cm + i) * N + bn + cn;
        *(float4*)&C[off]     = make_float4(acc[i][0], acc[i][1], acc[i][2], acc[i][3]);
        *(float4*)&C[off + 4] = make_float4(acc[i][4], acc[i][5], acc[i][6], acc[i][7]);
    }
}

// ---------------- fused delta: R (+)= Xf@Pw^T + Xa@Aw^T  (rows x 128) ----------------
__global__ __launch_bounds__(128) void k_delta(const float* __restrict__ Xf, const float* __restrict__ Xa,
                                               const float* __restrict__ Pw, const float* __restrict__ Aw,
                                               float* __restrict__ R, int accumulate) {
    __shared__ float xsf[16][68], xsa[16][68];
    __shared__ float wsp[16][132], wsa[16][132];
    int t = threadIdx.x;
    int r0 = blockIdx.x * 64;
    int ty = t >> 4, tx = t & 15;
    float acc[8][8] = {};
    for (int kb = 0; kb < 128; kb += 16) {
        for (int idx = t; idx < 64 * 16; idx += 128) {
            int r = idx >> 4, c = idx & 15;
            xsf[c][r] = Xf[(size_t)(r0 + r) * 128 + kb + c];
            xsa[c][r] = Xa[(size_t)(r0 + r) * 128 + kb + c];
        }
        for (int idx = t; idx < 128 * 16; idx += 128) {
            int d = idx >> 4, c = idx & 15;
            wsp[c][d] = Pw[d * 128 + kb + c];
            wsa[c][d] = Aw[d * 128 + kb + c];
        }
        __syncthreads();
#pragma unroll
        for (int c = 0; c < 16; c++) {
            float xf[8], xa[8], pw[8], aw[8];
            *(float4*)&xf[0] = *(const float4*)&xsf[c][ty * 8];
            *(float4*)&xf[4] = *(const float4*)&xsf[c][ty * 8 + 4];
            *(float4*)&xa[0] = *(const float4*)&xsa[c][ty * 8];
            *(float4*)&xa[4] = *(const float4*)&xsa[c][ty * 8 + 4];
            *(float4*)&pw[0] = *(const float4*)&wsp[c][tx * 8];
            *(float4*)&pw[4] = *(const float4*)&wsp[c][tx * 8 + 4];
            *(float4*)&aw[0] = *(const float4*)&wsa[c][tx * 8];
            *(float4*)&aw[4] = *(const float4*)&wsa[c][tx * 8 + 4];
#pragma unroll
            for (int i = 0; i < 8; i++)
#pragma unroll
                for (int j = 0; j < 8; j++)
                    acc[i][j] += xf[i] * pw[j] + xa[i] * aw[j];
        }
        __syncthreads();
    }
#pragma unroll
    for (int i = 0; i < 8; i++) {
        size_t o = (size_t)(r0 + ty * 8 + i) * 128 + tx * 8;
        if (accumulate) {
#pragma unroll
            for (int j = 0; j < 8; j++) R[o + j] += acc[i][j];
        } else {
            *(float4*)&R[o]     = make_float4(acc[i][0], acc[i][1], acc[i][2], acc[i][3]);
            *(float4*)&R[o + 4] = make_float4(acc[i][4], acc[i][5], acc[i][6], acc[i][7]);
        }
    }
}

// ---------------- final: out = LN(x + sigmoid(alpha)*res) * gamma + beta ----------------
__global__ void k_ln(const float* __restrict__ x, const float* __restrict__ gamma,
                     const float* __restrict__ beta, const float* __restrict__ alpha,
                     float* __restrict__ out) {
    int row = blockIdx.x * 8 + (threadIdx.x >> 5);
    int lane = threadIdx.x & 31;
    float gate = 1.0f / (1.0f + expf(-alpha[0]));
    size_t base = (size_t)row * CDIM;
    float h[4];
    float s = 0.f;
#pragma unroll
    for (int u = 0; u < 4; u++) {
        int c = lane + u * 32;
        h[u] = x[base + c] + gate * g_res[base + c];
        s += h[u];
    }
#pragma unroll
    for (int o = 16; o; o >>= 1) s += __shfl_xor_sync(0xffffffffu, s, o);
    float mu = s * (1.0f / CDIM);
    float v = 0.f;
#pragma unroll
    for (int u = 0; u < 4; u++) { float d = h[u] - mu; v += d * d; }
#pragma unroll
    for (int o = 16; o; o >>= 1) v += __shfl_xor_sync(0xffffffffu, v, o);
    float rs = rsqrtf(v * (1.0f / CDIM) + LN_EPS);
#pragma unroll
    for (int u = 0; u < 4; u++) {
        int c = lane + u * 32;
        out[base + c] = (h[u] - mu) * rs * gamma[c] + beta[c];
    }
}

// ---------------- host orchestration ----------------
extern "C" void kernel_launch(void* const* d_in, const int* in_sizes, int n_in,
                              void* d_out, int out_size) {
    const float* x     = (const float*)d_in[0];
    const float* prior = (const float*)d_in[1];
    const float* W1    = (const float*)d_in[2];
    const float* W2    = (const float*)d_in[3];
    const float* W3    = (const float*)d_in[4];
    const float* Pfw   = (const float*)d_in[5];
    const float* Awt   = (const float*)d_in[6];
    const float* gamma = (const float*)d_in[7];
    const float* beta  = (const float*)d_in[8];
    const float* alpha = (const float*)d_in[9];
    float* out = (float*)d_out;

    float *Rf, *attn, *Xf1, *Xa1, *Xf2, *Xa2, *res;
    cudaGetSymbolAddress((void**)&Rf,   g_Rf);
    cudaGetSymbolAddress((void**)&attn, g_attn);
    cudaGetSymbolAddress((void**)&Xf1,  g_Xf1);
    cudaGetSymbolAddress((void**)&Xa1,  g_Xa1);
    cudaGetSymbolAddress((void**)&Xf2,  g_Xf2);
    cudaGetSymbolAddress((void**)&Xa2,  g_Xa2);
    cudaGetSymbolAddress((void**)&res,  g_res);

    k_rowsum<<<NP, 256>>>(prior);
    k_scaleRf<<<4096, 256>>>(prior);

    for (int step = 0; step < 2; step++) {
        const float* Xf_in = step ? (const float*)Xf1 : x;
        const float* Xa_in = step ? (const float*)Xa1 : x;
        float* Xf_out = step ? Xf2 : Xf1;
        float* Xa_out = step ? Xa2 : Xa1;

        k_pool<<<NP, CDIM>>>(Xa_in);
        k_e1e3<<<NP, DDIM>>>(W1, W3);
        k_f<<<NP, DDIM>>>(W2);
        k_logits<<<dim3(32, 32), 256>>>();
        k_softmax<<<NP, 256>>>();
        k_topp<<<NP, 1024>>>();
        k_mask<<<4096, 256>>>();

        k_sgemm<<<dim3(64, 16), 256>>>(Rf,   Xf_in, Xf_out, NP, NCC, NP);
        k_sgemm<<<dim3(64, 16), 256>>>(attn, Xa_in, Xa_out, NP, NCC, NP);

        k_delta<<<2048, 128>>>(Xf_out, Xa_out,
                               Pfw + (size_t)step * CDIM * CDIM,
                               Awt + (size_t)step * CDIM * CDIM,
                               res, step);
    }

    k_ln<<<(int)(TOT / CDIM / 8), 256>>>(x, gamma, beta, alpha, out);
}

// round 3
// speedup vs baseline: 3.0137x; 3.0137x over previous
#include <cuda_runtime.h>
#include <cuda_bf16.h>
#include <cstdint>

#define NP 2048
#define NC 64
#define CDIM 128
#define DDIM 64
#define NCC (NC*CDIM)              /* 8192 */
#define TOT ((size_t)NP*NCC)       /* 16777216 */
#define P_TOPP 0.9f
#define LN_EPS 1e-5f

typedef __nv_bfloat16 bf16;

// ---------------- scratch (device globals; allowed) ----------------
__device__ __align__(128) bf16  g_RfB[(size_t)NP*NP];
__device__ __align__(128) float g_attn[(size_t)NP*NP];
__device__ __align__(128) bf16  g_attnB[(size_t)NP*NP];
__device__ float g_rowinv[NP];
__device__ float g_pooled[NP*CDIM];
__device__ float g_e1[NP*DDIM];
__device__ float g_e3[NP*DDIM];
__device__ float g_fm[NP*DDIM];
__device__ float g_thr[NP];
__device__ float g_scl[NP];
__device__ __align__(128) bf16 g_xT[TOT];
__device__ __align__(128) bf16 g_Xf1[TOT];
__device__ __align__(128) bf16 g_Xa1[TOT];
__device__ __align__(128) bf16 g_Xf2[TOT];
__device__ __align__(128) bf16 g_Xa2[TOT];
__device__ __align__(128) bf16 g_Xf1T[TOT];
__device__ __align__(128) bf16 g_Xa1T[TOT];
__device__ __align__(128) float g_res[TOT];

// ---------------- prior row-normalization ----------------
__global__ void k_rowsum(const float* __restrict__ prior) {
    __shared__ float red[256];
    int row = blockIdx.x, t = threadIdx.x;
    const float* p = prior + (size_t)row * NP;
    float s = 0.f;
    for (int j = t; j < NP; j += 256) s += p[j];
    red[t] = s; __syncthreads();
    for (int o = 128; o; o >>= 1) { if (t < o) red[t] += red[t + o]; __syncthreads(); }
    if (t == 0) g_rowinv[row] = 1.0f / fmaxf(red[0], 1e-12f);
}

__global__ void k_scaleRf(const float* __restrict__ prior) {
    size_t idx = (size_t)blockIdx.x * blockDim.x + threadIdx.x;
    size_t stride = (size_t)gridDim.x * blockDim.x;
    for (size_t i = idx; i < (size_t)NP * NP; i += stride)
        g_RfB[i] = __float2bfloat16(prior[i] * g_rowinv[i >> 11]);
}

// ---------------- transposes ----------------
__global__ void k_transpose_f2b(const float* __restrict__ in, bf16* __restrict__ out,
                                int R, int Ccols) {
    __shared__ float tile[32][33];
    int bx = blockIdx.x * 32, by = blockIdx.y * 32;
    int tx = threadIdx.x, ty = threadIdx.y;   // 32 x 8
#pragma unroll
    for (int j = 0; j < 32; j += 8)
        tile[ty + j][tx] = in[(size_t)(by + ty + j) * Ccols + bx + tx];
    __syncthreads();
#pragma unroll
    for (int j = 0; j < 32; j += 8)
        out[(size_t)(bx + ty + j) * R + by + tx] = __float2bfloat16(tile[tx][ty + j]);
}

__global__ void k_transpose_b2b(const bf16* __restrict__ in, bf16* __restrict__ out,
                                int R, int Ccols) {
    __shared__ float tile[32][33];
    int bx = blockIdx.x * 32, by = blockIdx.y * 32;
    int tx = threadIdx.x, ty = threadIdx.y;
#pragma unroll
    for (int j = 0; j < 32; j += 8)
        tile[ty + j][tx] = __bfloat162float(in[(size_t)(by + ty + j) * Ccols + bx + tx]);
    __syncthreads();
#pragma unroll
    for (int j = 0; j < 32; j += 8)
        out[(size_t)(bx + ty + j) * R + by + tx] = __float2bfloat16(tile[tx][ty + j]);
}

// ---------------- mean pool over protein axis ----------------
__global__ void k_pool_f(const float* __restrict__ X) {
    int i = blockIdx.x, c = threadIdx.x;
    const float* p = X + (size_t)i * NCC + c;
    float s = 0.f;
#pragma unroll
    for (int k = 0; k < NC; k++) s += p[k * CDIM];
    g_pooled[i * CDIM + c] = s * (1.0f / NC);
}

__global__ void k_pool_b(const bf16* __restrict__ X) {
    int i = blockIdx.x, c = threadIdx.x;
    const bf16* p = X + (size_t)i * NCC + c;
    float s = 0.f;
#pragma unroll
    for (int k = 0; k < NC; k++) s += __bfloat162float(p[k * CDIM]);
    g_pooled[i * CDIM + c] = s * (1.0f / NC);
}

// ---------------- small projections ----------------
__global__ void k_e1e3(const float* __restrict__ W1, const float* __restrict__ W3) {
    int i = blockIdx.x, d = threadIdx.x;  // 64 threads
    __shared__ float p[CDIM];
    p[d] = g_pooled[i * CDIM + d];
    p[d + 64] = g_pooled[i * CDIM + d + 64];
    __syncthreads();
    float s1 = 0.f, s3 = 0.f;
#pragma unroll 4
    for (int c = 0; c < CDIM; c++) {
        float pc = p[c];
        s1 += pc * W1[d * CDIM + c];
        s3 += pc * W3[d * CDIM + c];
    }
    g_e1[i * DDIM + d] = s1;
    g_e3[i * DDIM + d] = s3;
}

__global__ void k_f(const float* __restrict__ W2) {
    int i = blockIdx.x, d = threadIdx.x;  // 64 threads
    __shared__ float e[DDIM];
    e[d] = g_e1[i * DDIM + d];
    __syncthreads();
    float s = 0.f;
#pragma unroll 4
    for (int k = 0; k < DDIM; k++) s += e[k] * W2[d * DDIM + k];
    g_fm[i * DDIM + d] = s;
}

// logits[i,n] = sum_k f[i,k]*e3[n,k]
__global__ __launch_bounds__(256) void k_logits() {
    __shared__ float Fs[64][65];
    __shared__ float Es[64][65];
    int bm = blockIdx.y * 64, bn = blockIdx.x * 64;
    int t = threadIdx.x;
    for (int idx = t; idx < 64 * 64; idx += 256) {
        int r = idx >> 6, c = idx & 63;
        Fs[r][c] = g_fm[(bm + r) * 64 + c];
        Es[r][c] = g_e3[(bn + r) * 64 + c];
    }
    __syncthreads();
    int tx = t & 15, ty = t >> 4;
    float acc[4][4] = {};
    for (int k = 0; k < 64; k++) {
        float a[4], b[4];
#pragma unroll
        for (int r = 0; r < 4; r++) { a[r] = Fs[ty * 4 + r][k]; b[r] = Es[tx * 4 + r][k]; }
#pragma unroll
        for (int i = 0; i < 4; i++)
#pragma unroll
            for (int j = 0; j < 4; j++) acc[i][j] += a[i] * b[j];
    }
#pragma unroll
    for (int i = 0; i < 4; i++)
#pragma unroll
        for (int j = 0; j < 4; j++)
            g_attn[(size_t)(bm + ty * 4 + i) * NP + bn + tx * 4 + j] = acc[i][j];
}

// ---------------- row softmax ----------------
__global__ void k_softmax() {
    int row = blockIdx.x, t = threadIdx.x;
    float* a = g_attn + (size_t)row * NP;
    __shared__ float red[256];
    float m = -1e30f;
    for (int j = t; j < NP; j += 256) m = fmaxf(m, a[j]);
    red[t] = m; __syncthreads();
    for (int o = 128; o; o >>= 1) { if (t < o) red[t] = fmaxf(red[t], red[t + o]); __syncthreads(); }
    m = red[0];
    __syncthreads();
    float s = 0.f;
    for (int j = t; j < NP; j += 256) { float e = expf(a[j] - m); a[j] = e; s += e; }
    red[t] = s; __syncthreads();
    for (int o = 128; o; o >>= 1) { if (t < o) red[t] += red[t + o]; __syncthreads(); }
    float inv = 1.0f / red[0];
    for (int j = t; j < NP; j += 256) a[j] *= inv;
}

// ---------------- top-p ----------------
__global__ __launch_bounds__(1024) void k_topp() {
    __shared__ float s[2048];
    __shared__ float cs[2048];
    __shared__ int kmax;
    int row = blockIdx.x, t = threadIdx.x;
    const float* a = g_attn + (size_t)row * NP;
    s[t] = a[t]; s[t + 1024] = a[t + 1024];
    __syncthreads();
    for (int k = 2; k <= 2048; k <<= 1) {
        for (int j = k >> 1; j > 0; j >>= 1) {
#pragma unroll
            for (int u = 0; u < 2; u++) {
                int i = t + u * 1024;
                int ixj = i ^ j;
                if (ixj > i) {
                    float xi = s[i], xj = s[ixj];
                    bool descBlk = ((i & k) == 0);
                    bool sw = descBlk ? (xi < xj) : (xi > xj);
                    if (sw) { s[i] = xj; s[ixj] = xi; }
                }
            }
            __syncthreads();
        }
    }
    cs[t] = s[t]; cs[t + 1024] = s[t + 1024];
    __syncthreads();
    for (int off = 1; off < 2048; off <<= 1) {
        float v0 = (t >= off) ? cs[t - off] : 0.f;
        int t1 = t + 1024;
        float v1 = (t1 >= off) ? cs[t1 - off] : 0.f;
        __syncthreads();
        cs[t] += v0; cs[t1] += v1;
        __syncthreads();
    }
    if (t == 0) kmax = 0;
    __syncthreads();
    if (cs[t] - s[t] < P_TOPP) atomicMax(&kmax, t);
    if (cs[t + 1024] - s[t + 1024] < P_TOPP) atomicMax(&kmax, t + 1024);
    __syncthreads();
    float thr = s[kmax];
    float part = (s[t] >= thr ? s[t] : 0.f) + (s[t + 1024] >= thr ? s[t + 1024] : 0.f);
    __syncthreads();
    cs[t] = part; __syncthreads();
    for (int o = 512; o; o >>= 1) { if (t < o) cs[t] += cs[t + o]; __syncthreads(); }
    if (t == 0) {
        g_thr[row] = thr;
        g_scl[row] = 1.0f / fmaxf(cs[0], 1e-12f);
    }
}

// sparsify + renormalize -> bf16 attnB
__global__ void k_mask() {
    size_t idx = (size_t)blockIdx.x * blockDim.x + threadIdx.x;
    size_t stride = (size_t)gridDim.x * blockDim.x;
    for (size_t i = idx; i < (size_t)NP * NP; i += stride) {
        int r = (int)(i >> 11);
        float v = g_attn[i];
        g_attnB[i] = __float2bfloat16((v >= g_thr[r]) ? v * g_scl[r] : 0.0f);
    }
}

// ---------------- bf16 tensor-core GEMM ----------------
// C[m,n] = sum_k A[m,k]*BT[n,k]; A [M][K], BT [N][K], C [M][N], all bf16 row-major.
// Tiles 128x128x32, 8 warps (4m x 2n), warp tile 32x64, fp32 accum.
#define CP_ASYNC16(dst_u32, src_ptr) \
    asm volatile("cp.async.cg.shared.global [%0], [%1], 16;\n" :: "r"(dst_u32), "l"(src_ptr))
#define MMA16816(d, a, b) \
    asm volatile("mma.sync.aligned.m16n8k16.row.col.f32.bf16.bf16.f32 " \
                 "{%0,%1,%2,%3},{%4,%5,%6,%7},{%8,%9},{%0,%1,%2,%3};" \
                 : "+f"(d[0]), "+f"(d[1]), "+f"(d[2]), "+f"(d[3]) \
                 : "r"(a[0]), "r"(a[1]), "r"(a[2]), "r"(a[3]), "r"(b[0]), "r"(b[1]))

__global__ __launch_bounds__(256) void k_gemm_bf16(
    const bf16* __restrict__ A, const bf16* __restrict__ BT, bf16* __restrict__ C,
    int M, int N, int K)
{
    // 128 rows x 32 bf16 per tile; row stride padded to 20 words (16 data + 4 pad)
    __shared__ uint32_t As[2][128 * 20];
    __shared__ uint32_t Bs[2][128 * 20];
    int t = threadIdx.x;
    int bm = blockIdx.y << 7, bn = blockIdx.x << 7;
    int warp = t >> 5, lane = t & 31;
    int wm = warp & 3, wn = warp >> 2;
    int g = lane >> 2, tq = lane & 3;

    // loader: 256 threads; each owns rows (t>>2) and (t>>2)+64, 16B chunk (t&3)
    int lrow = t >> 2, lchunk = t & 3;
    const bf16* gA0 = A  + (size_t)(bm + lrow) * K      + lchunk * 8;
    const bf16* gA1 = A  + (size_t)(bm + lrow + 64) * K + lchunk * 8;
    const bf16* gB0 = BT + (size_t)(bn + lrow) * K      + lchunk * 8;
    const bf16* gB1 = BT + (size_t)(bn + lrow + 64) * K + lchunk * 8;
    uint32_t sA0[2], sA1[2], sB0[2], sB1[2];
#pragma unroll
    for (int b = 0; b < 2; b++) {
        sA0[b] = (uint32_t)__cvta_generic_to_shared(&As[b][lrow * 20 + lchunk * 4]);
        sA1[b] = (uint32_t)__cvta_generic_to_shared(&As[b][(lrow + 64) * 20 + lchunk * 4]);
        sB0[b] = (uint32_t)__cvta_generic_to_shared(&Bs[b][lrow * 20 + lchunk * 4]);
        sB1[b] = (uint32_t)__cvta_generic_to_shared(&Bs[b][(lrow + 64) * 20 + lchunk * 4]);
    }

    float acc[2][8][4] = {};

    int NT = K >> 5;
    CP_ASYNC16(sA0[0], gA0);
    CP_ASYNC16(sA1[0], gA1);
    CP_ASYNC16(sB0[0], gB0);
    CP_ASYNC16(sB1[0], gB1);
    asm volatile("cp.async.commit_group;\n" ::: "memory");

    for (int it = 0; it < NT; it++) {
        int buf = it & 1;
        if (it + 1 < NT) {
            size_t ko = (size_t)(it + 1) << 5;
            CP_ASYNC16(sA0[buf ^ 1], gA0 + ko);
            CP_ASYNC16(sA1[buf ^ 1], gA1 + ko);
            CP_ASYNC16(sB0[buf ^ 1], gB0 + ko);
            CP_ASYNC16(sB1[buf ^ 1], gB1 + ko);
            asm volatile("cp.async.commit_group;\n" ::: "memory");
            asm volatile("cp.async.wait_group 1;\n" ::: "memory");
        } else {
            asm volatile("cp.async.wait_group 0;\n" ::: "memory");
        }
        __syncthreads();

#pragma unroll
        for (int s = 0; s < 2; s++) {
            uint32_t a[2][4], b[8][2];
#pragma unroll
            for (int mi = 0; mi < 2; mi++) {
                int r = (wm * 32 + mi * 16 + g) * 20 + s * 8 + tq;
                a[mi][0] = As[buf][r];
                a[mi][1] = As[buf][r + 8 * 20];
                a[mi][2] = As[buf][r + 4];
                a[mi][3] = As[buf][r + 8 * 20 + 4];
            }
#pragma unroll
            for (int ni = 0; ni < 8; ni++) {
                int r = (wn * 64 + ni * 8 + g) * 20 + s * 8 + tq;
                b[ni][0] = Bs[buf][r];
                b[ni][1] = Bs[buf][r + 4];
            }
#pragma unroll
            for (int mi = 0; mi < 2; mi++)
#pragma unroll
                for (int ni = 0; ni < 8; ni++)
                    MMA16816(acc[mi][ni], a[mi], b[ni]);
        }
        __syncthreads();
    }

#pragma unroll
    for (int mi = 0; mi < 2; mi++) {
#pragma unroll
        for (int ni = 0; ni < 8; ni++) {
            int row = bm + wm * 32 + mi * 16 + g;
            int col = bn + wn * 64 + ni * 8 + tq * 2;
            __nv_bfloat162* p0 = (__nv_bfloat162*)&C[(size_t)row * N + col];
            __nv_bfloat162* p1 = (__nv_bfloat162*)&C[(size_t)(row + 8) * N + col];
            *p0 = __float22bfloat162_rn(make_float2(acc[mi][ni][0], acc[mi][ni][1]));
            *p1 = __float22bfloat162_rn(make_float2(acc[mi][ni][2], acc[mi][ni][3]));
        }
    }
}

// ---------------- fused delta: R (+)= Xf@Pw^T + Xa@Aw^T (bf16 in, fp32 accum) ----
__global__ __launch_bounds__(128) void k_delta(const bf16* __restrict__ Xf, const bf16* __restrict__ Xa,
                                               const float* __restrict__ Pw, const float* __restrict__ Aw,
                                               float* __restrict__ R, int accumulate) {
    __shared__ float xsf[16][68], xsa[16][68];
    __shared__ float wsp[16][132], wsa[16][132];
    int t = threadIdx.x;
    int r0 = blockIdx.x * 64;
    int ty = t >> 4, tx = t & 15;
    float acc[8][8] = {};
    for (int kb = 0; kb < 128; kb += 16) {
        for (int idx = t; idx < 64 * 16; idx += 128) {
            int r = idx >> 4, c = idx & 15;
            xsf[c][r] = __bfloat162float(Xf[(size_t)(r0 + r) * 128 + kb + c]);
            xsa[c][r] = __bfloat162float(Xa[(size_t)(r0 + r) * 128 + kb + c]);
        }
        for (int idx = t; idx < 128 * 16; idx += 128) {
            int d = idx >> 4, c = idx & 15;
            wsp[c][d] = Pw[d * 128 + kb + c];
            wsa[c][d] = Aw[d * 128 + kb + c];
        }
        __syncthreads();
#pragma unroll
        for (int c = 0; c < 16; c++) {
            float xf[8], xa[8], pw[8], aw[8];
            *(float4*)&xf[0] = *(const float4*)&xsf[c][ty * 8];
            *(float4*)&xf[4] = *(const float4*)&xsf[c][ty * 8 + 4];
            *(float4*)&xa[0] = *(const float4*)&xsa[c][ty * 8];
            *(float4*)&xa[4] = *(const float4*)&xsa[c][ty * 8 + 4];
            *(float4*)&pw[0] = *(const float4*)&wsp[c][tx * 8];
            *(float4*)&pw[4] = *(const float4*)&wsp[c][tx * 8 + 4];
            *(float4*)&aw[0] = *(const float4*)&wsa[c][tx * 8];
            *(float4*)&aw[4] = *(const float4*)&wsa[c][tx * 8 + 4];
#pragma unroll
            for (int i = 0; i < 8; i++)
#pragma unroll
                for (int j = 0; j < 8; j++)
                    acc[i][j] += xf[i] * pw[j] + xa[i] * aw[j];
        }
        __syncthreads();
    }
#pragma unroll
    for (int i = 0; i < 8; i++) {
        size_t o = (size_t)(r0 + ty * 8 + i) * 128 + tx * 8;
        if (accumulate) {
#pragma unroll
            for (int j = 0; j < 8; j++) R[o + j] += acc[i][j];
        } else {
            *(float4*)&R[o]     = make_float4(acc[i][0], acc[i][1], acc[i][2], acc[i][3]);
            *(float4*)&R[o + 4] = make_float4(acc[i][4], acc[i][5], acc[i][6], acc[i][7]);
        }
    }
}

// ---------------- final: out = LN(x + sigmoid(alpha)*res) ----------------
__global__ void k_ln(const float* __restrict__ x, const float* __restrict__ gamma,
                     const float* __restrict__ beta, const float* __restrict__ alpha,
                     float* __restrict__ out) {
    int row = blockIdx.x * 8 + (threadIdx.x >> 5);
    int lane = threadIdx.x & 31;
    float gate = 1.0f / (1.0f + expf(-alpha[0]));
    size_t base = (size_t)row * CDIM;
    float h[4];
    float s = 0.f;
#pragma unroll
    for (int u = 0; u < 4; u++) {
        int c = lane + u * 32;
        h[u] = x[base + c] + gate * g_res[base + c];
        s += h[u];
    }
#pragma unroll
    for (int o = 16; o; o >>= 1) s += __shfl_xor_sync(0xffffffffu, s, o);
    float mu = s * (1.0f / CDIM);
    float v = 0.f;
#pragma unroll
    for (int u = 0; u < 4; u++) { float d = h[u] - mu; v += d * d; }
#pragma unroll
    for (int o = 16; o; o >>= 1) v += __shfl_xor_sync(0xffffffffu, v, o);
    float rs = rsqrtf(v * (1.0f / CDIM) + LN_EPS);
#pragma unroll
    for (int u = 0; u < 4; u++) {
        int c = lane + u * 32;
        out[base + c] = (h[u] - mu) * rs * gamma[c] + beta[c];
    }
}

// ---------------- host orchestration ----------------
extern "C" void kernel_launch(void* const* d_in, const int* in_sizes, int n_in,
                              void* d_out, int out_size) {
    const float* x     = (const float*)d_in[0];
    const float* prior = (const float*)d_in[1];
    const float* W1    = (const float*)d_in[2];
    const float* W2    = (const float*)d_in[3];
    const float* W3    = (const float*)d_in[4];
    const float* Pfw   = (const float*)d_in[5];
    const float* Awt   = (const float*)d_in[6];
    const float* gamma = (const float*)d_in[7];
    const float* beta  = (const float*)d_in[8];
    const float* alpha = (const float*)d_in[9];
    float* out = (float*)d_out;

    bf16 *RfB, *attnB, *xT, *Xf1, *Xa1, *Xf2, *Xa2, *Xf1T, *Xa1T;
    float *res;
    cudaGetSymbolAddress((void**)&RfB,   g_RfB);
    cudaGetSymbolAddress((void**)&attnB, g_attnB);
    cudaGetSymbolAddress((void**)&xT,    g_xT);
    cudaGetSymbolAddress((void**)&Xf1,   g_Xf1);
    cudaGetSymbolAddress((void**)&Xa1,   g_Xa1);
    cudaGetSymbolAddress((void**)&Xf2,   g_Xf2);
    cudaGetSymbolAddress((void**)&Xa2,   g_Xa2);
    cudaGetSymbolAddress((void**)&Xf1T,  g_Xf1T);
    cudaGetSymbolAddress((void**)&Xa1T,  g_Xa1T);
    cudaGetSymbolAddress((void**)&res,   g_res);

    k_rowsum<<<NP, 256>>>(prior);
    k_scaleRf<<<4096, 256>>>(prior);
    k_transpose_f2b<<<dim3(NCC / 32, NP / 32), dim3(32, 8)>>>(x, xT, NP, NCC);

    for (int step = 0; step < 2; step++) {
        if (step == 0) k_pool_f<<<NP, CDIM>>>(x);
        else           k_pool_b<<<NP, CDIM>>>(Xa1);
        k_e1e3<<<NP, DDIM>>>(W1, W3);
        k_f<<<NP, DDIM>>>(W2);
        k_logits<<<dim3(32, 32), 256>>>();
        k_softmax<<<NP, 256>>>();
        k_topp<<<NP, 1024>>>();
        k_mask<<<4096, 256>>>();

        const bf16* BT_f = step ? (const bf16*)Xf1T : (const bf16*)xT;
        const bf16* BT_a = step ? (const bf16*)Xa1T : (const bf16*)xT;
        bf16* Xf_out = step ? Xf2 : Xf1;
        bf16* Xa_out = step ? Xa2 : Xa1;

        k_gemm_bf16<<<dim3(NCC / 128, NP / 128), 256>>>(RfB,   BT_f, Xf_out, NP, NCC, NP);
        k_gemm_bf16<<<dim3(NCC / 128, NP / 128), 256>>>(attnB, BT_a, Xa_out, NP, NCC, NP);

        k_delta<<<2048, 128>>>(Xf_out, Xa_out,
                               Pfw + (size_t)step * CDIM * CDIM,
                               Awt + (size_t)step * CDIM * CDIM,
                               res, step);

        if (step == 0) {
            k_transpose_b2b<<<dim3(NCC / 32, NP / 32), dim3(32, 8)>>>(Xf1, Xf1T, NP, NCC);
            k_transpose_b2b<<<dim3(NCC / 32, NP / 32), dim3(32, 8)>>>(Xa1, Xa1T, NP, NCC);
        }
    }

    k_ln<<<(int)(TOT / CDIM / 8), 256>>>(x, gamma, beta, alpha, out);
}

// round 4
// speedup vs baseline: 3.0143x; 1.0002x over previous
#include <cuda_runtime.h>
#include <cuda_bf16.h>
#include <cstdint>

#define NP 2048
#define NC 64
#define CDIM 128
#define DDIM 64
#define NCC (NC*CDIM)              /* 8192 */
#define TOT ((size_t)NP*NCC)       /* 16777216 */
#define P_TOPP 0.9f
#define LN_EPS 1e-5f

typedef __nv_bfloat16 bf16;

// ---------------- scratch (device globals; allowed) ----------------
__device__ __align__(128) bf16  g_RfB[(size_t)NP*NP];
__device__ __align__(128) float g_attn[(size_t)NP*NP];
__device__ __align__(128) bf16  g_attnB[(size_t)NP*NP];
__device__ float g_rowinv[NP];
__device__ float g_pooled[NP*CDIM];
__device__ float g_e1[NP*DDIM];
__device__ float g_e3[NP*DDIM];
__device__ float g_fm[NP*DDIM];
__device__ float g_thr[NP];
__device__ float g_scl[NP];
__device__ __align__(128) bf16 g_xT[TOT];
__device__ __align__(128) bf16 g_Xf1[TOT];
__device__ __align__(128) bf16 g_Xa1[TOT];
__device__ __align__(128) bf16 g_Xf2[TOT];
__device__ __align__(128) bf16 g_Xa2[TOT];
__device__ __align__(128) bf16 g_Xf1T[TOT];
__device__ __align__(128) bf16 g_Xa1T[TOT];
__device__ __align__(128) float g_res[TOT];

// ---------------- prior row-normalization ----------------
__global__ void k_rowsum(const float* __restrict__ prior) {
    __shared__ float red[256];
    int row = blockIdx.x, t = threadIdx.x;
    const float* p = prior + (size_t)row * NP;
    float s = 0.f;
    for (int j = t; j < NP; j += 256) s += p[j];
    red[t] = s; __syncthreads();
    for (int o = 128; o; o >>= 1) { if (t < o) red[t] += red[t + o]; __syncthreads(); }
    if (t == 0) g_rowinv[row] = 1.0f / fmaxf(red[0], 1e-12f);
}

__global__ void k_scaleRf(const float* __restrict__ prior) {
    size_t idx = (size_t)blockIdx.x * blockDim.x + threadIdx.x;
    size_t stride = (size_t)gridDim.x * blockDim.x;
    for (size_t i = idx; i < (size_t)NP * NP; i += stride)
        g_RfB[i] = __float2bfloat16(prior[i] * g_rowinv[i >> 11]);
}

// ---------------- transposes ----------------
__global__ void k_transpose_f2b(const float* __restrict__ in, bf16* __restrict__ out,
                                int R, int Ccols) {
    __shared__ float tile[32][33];
    int bx = blockIdx.x * 32, by = blockIdx.y * 32;
    int tx = threadIdx.x, ty = threadIdx.y;   // 32 x 8
#pragma unroll
    for (int j = 0; j < 32; j += 8)
        tile[ty + j][tx] = in[(size_t)(by + ty + j) * Ccols + bx + tx];
    __syncthreads();
#pragma unroll
    for (int j = 0; j < 32; j += 8)
        out[(size_t)(bx + ty + j) * R + by + tx] = __float2bfloat16(tile[tx][ty + j]);
}

__global__ void k_transpose_b2b(const bf16* __restrict__ in, bf16* __restrict__ out,
                                int R, int Ccols) {
    __shared__ float tile[32][33];
    int bx = blockIdx.x * 32, by = blockIdx.y * 32;
    int tx = threadIdx.x, ty = threadIdx.y;
#pragma unroll
    for (int j = 0; j < 32; j += 8)
        tile[ty + j][tx] = __bfloat162float(in[(size_t)(by + ty + j) * Ccols + bx + tx]);
    __syncthreads();
#pragma unroll
    for (int j = 0; j < 32; j += 8)
        out[(size_t)(bx + ty + j) * R + by + tx] = __float2bfloat16(tile[tx][ty + j]);
}

// ---------------- mean pool over protein axis ----------------
__global__ void k_pool_f(const float* __restrict__ X) {
    int i = blockIdx.x, c = threadIdx.x;
    const float* p = X + (size_t)i * NCC + c;
    float s = 0.f;
#pragma unroll
    for (int k = 0; k < NC; k++) s += p[k * CDIM];
    g_pooled[i * CDIM + c] = s * (1.0f / NC);
}

__global__ void k_pool_b(const bf16* __restrict__ X) {
    int i = blockIdx.x, c = threadIdx.x;
    const bf16* p = X + (size_t)i * NCC + c;
    float s = 0.f;
#pragma unroll
    for (int k = 0; k < NC; k++) s += __bfloat162float(p[k * CDIM]);
    g_pooled[i * CDIM + c] = s * (1.0f / NC);
}

// ---------------- small projections ----------------
__global__ void k_e1e3(const float* __restrict__ W1, const float* __restrict__ W3) {
    int i = blockIdx.x, d = threadIdx.x;  // 64 threads
    __shared__ float p[CDIM];
    p[d] = g_pooled[i * CDIM + d];
    p[d + 64] = g_pooled[i * CDIM + d + 64];
    __syncthreads();
    float s1 = 0.f, s3 = 0.f;
#pragma unroll 4
    for (int c = 0; c < CDIM; c++) {
        float pc = p[c];
        s1 += pc * W1[d * CDIM + c];
        s3 += pc * W3[d * CDIM + c];
    }
    g_e1[i * DDIM + d] = s1;
    g_e3[i * DDIM + d] = s3;
}

__global__ void k_f(const float* __restrict__ W2) {
    int i = blockIdx.x, d = threadIdx.x;  // 64 threads
    __shared__ float e[DDIM];
    e[d] = g_e1[i * DDIM + d];
    __syncthreads();
    float s = 0.f;
#pragma unroll 4
    for (int k = 0; k < DDIM; k++) s += e[k] * W2[d * DDIM + k];
    g_fm[i * DDIM + d] = s;
}

// logits[i,n] = sum_k f[i,k]*e3[n,k]
__global__ __launch_bounds__(256) void k_logits() {
    __shared__ float Fs[64][65];
    __shared__ float Es[64][65];
    int bm = blockIdx.y * 64, bn = blockIdx.x * 64;
    int t = threadIdx.x;
    for (int idx = t; idx < 64 * 64; idx += 256) {
        int r = idx >> 6, c = idx & 63;
        Fs[r][c] = g_fm[(bm + r) * 64 + c];
        Es[r][c] = g_e3[(bn + r) * 64 + c];
    }
    __syncthreads();
    int tx = t & 15, ty = t >> 4;
    float acc[4][4] = {};
    for (int k = 0; k < 64; k++) {
        float a[4], b[4];
#pragma unroll
        for (int r = 0; r < 4; r++) { a[r] = Fs[ty * 4 + r][k]; b[r] = Es[tx * 4 + r][k]; }
#pragma unroll
        for (int i = 0; i < 4; i++)
#pragma unroll
            for (int j = 0; j < 4; j++) acc[i][j] += a[i] * b[j];
    }
#pragma unroll
    for (int i = 0; i < 4; i++)
#pragma unroll
        for (int j = 0; j < 4; j++)
            g_attn[(size_t)(bm + ty * 4 + i) * NP + bn + tx * 4 + j] = acc[i][j];
}

// ---------------- row softmax ----------------
__global__ void k_softmax() {
    int row = blockIdx.x, t = threadIdx.x;
    float* a = g_attn + (size_t)row * NP;
    __shared__ float red[256];
    float m = -1e30f;
    for (int j = t; j < NP; j += 256) m = fmaxf(m, a[j]);
    red[t] = m; __syncthreads();
    for (int o = 128; o; o >>= 1) { if (t < o) red[t] = fmaxf(red[t], red[t + o]); __syncthreads(); }
    m = red[0];
    __syncthreads();
    float s = 0.f;
    for (int j = t; j < NP; j += 256) { float e = expf(a[j] - m); a[j] = e; s += e; }
    red[t] = s; __syncthreads();
    for (int o = 128; o; o >>= 1) { if (t < o) red[t] += red[t + o]; __syncthreads(); }
    float inv = 1.0f / red[0];
    for (int j = t; j < NP; j += 256) a[j] *= inv;
}

// ---------------- top-p ----------------
__global__ __launch_bounds__(1024) void k_topp() {
    __shared__ float s[2048];
    __shared__ float cs[2048];
    __shared__ int kmax;
    int row = blockIdx.x, t = threadIdx.x;
    const float* a = g_attn + (size_t)row * NP;
    s[t] = a[t]; s[t + 1024] = a[t + 1024];
    __syncthreads();
    for (int k = 2; k <= 2048; k <<= 1) {
        for (int j = k >> 1; j > 0; j >>= 1) {
#pragma unroll
            for (int u = 0; u < 2; u++) {
                int i = t + u * 1024;
                int ixj = i ^ j;
                if (ixj > i) {
                    float xi = s[i], xj = s[ixj];
                    bool descBlk = ((i & k) == 0);
                    bool sw = descBlk ? (xi < xj) : (xi > xj);
                    if (sw) { s[i] = xj; s[ixj] = xi; }
                }
            }
            __syncthreads();
        }
    }
    cs[t] = s[t]; cs[t + 1024] = s[t + 1024];
    __syncthreads();
    for (int off = 1; off < 2048; off <<= 1) {
        float v0 = (t >= off) ? cs[t - off] : 0.f;
        int t1 = t + 1024;
        float v1 = (t1 >= off) ? cs[t1 - off] : 0.f;
        __syncthreads();
        cs[t] += v0; cs[t1] += v1;
        __syncthreads();
    }
    if (t == 0) kmax = 0;
    __syncthreads();
    if (cs[t] - s[t] < P_TOPP) atomicMax(&kmax, t);
    if (cs[t + 1024] - s[t + 1024] < P_TOPP) atomicMax(&kmax, t + 1024);
    __syncthreads();
    float thr = s[kmax];
    float part = (s[t] >= thr ? s[t] : 0.f) + (s[t + 1024] >= thr ? s[t + 1024] : 0.f);
    __syncthreads();
    cs[t] = part; __syncthreads();
    for (int o = 512; o; o >>= 1) { if (t < o) cs[t] += cs[t + o]; __syncthreads(); }
    if (t == 0) {
        g_thr[row] = thr;
        g_scl[row] = 1.0f / fmaxf(cs[0], 1e-12f);
    }
}

// sparsify + renormalize -> bf16 attnB
__global__ void k_mask() {
    size_t idx = (size_t)blockIdx.x * blockDim.x + threadIdx.x;
    size_t stride = (size_t)gridDim.x * blockDim.x;
    for (size_t i = idx; i < (size_t)NP * NP; i += stride) {
        int r = (int)(i >> 11);
        float v = g_attn[i];
        g_attnB[i] = __float2bfloat16((v >= g_thr[r]) ? v * g_scl[r] : 0.0f);
    }
}

// ---------------- bf16 tensor-core GEMM ----------------
// C[m,n] = sum_k A[m,k]*BT[n,k]; A [M][K], BT [N][K], C [M][N], all bf16 row-major.
// Tiles 128x128x32, 8 warps (4m x 2n), warp tile 32x64, fp32 accum.
#define CP_ASYNC16(dst_u32, src_ptr) \
    asm volatile("cp.async.cg.shared.global [%0], [%1], 16;\n" :: "r"(dst_u32), "l"(src_ptr))
#define MMA16816(d, a, b) \
    asm volatile("mma.sync.aligned.m16n8k16.row.col.f32.bf16.bf16.f32 " \
                 "{%0,%1,%2,%3},{%4,%5,%6,%7},{%8,%9},{%0,%1,%2,%3};" \
                 : "+f"(d[0]), "+f"(d[1]), "+f"(d[2]), "+f"(d[3]) \
                 : "r"(a[0]), "r"(a[1]), "r"(a[2]), "r"(a[3]), "r"(b[0]), "r"(b[1]))

__global__ __launch_bounds__(256) void k_gemm_bf16(
    const bf16* __restrict__ A, const bf16* __restrict__ BT, bf16* __restrict__ C,
    int M, int N, int K)
{
    // 128 rows x 32 bf16 per tile; row stride padded to 20 words (16 data + 4 pad)
    __shared__ uint32_t As[2][128 * 20];
    __shared__ uint32_t Bs[2][128 * 20];
    int t = threadIdx.x;
    int bm = blockIdx.y << 7, bn = blockIdx.x << 7;
    int warp = t >> 5, lane = t & 31;
    int wm = warp & 3, wn = warp >> 2;
    int g = lane >> 2, tq = lane & 3;

    // loader: 256 threads; each owns rows (t>>2) and (t>>2)+64, 16B chunk (t&3)
    int lrow = t >> 2, lchunk = t & 3;
    const bf16* gA0 = A  + (size_t)(bm + lrow) * K      + lchunk * 8;
    const bf16* gA1 = A  + (size_t)(bm + lrow + 64) * K + lchunk * 8;
    const bf16* gB0 = BT + (size_t)(bn + lrow) * K      + lchunk * 8;
    const bf16* gB1 = BT + (size_t)(bn + lrow + 64) * K + lchunk * 8;
    uint32_t sA0[2], sA1[2], sB0[2], sB1[2];
#pragma unroll
    for (int b = 0; b < 2; b++) {
        sA0[b] = (uint32_t)__cvta_generic_to_shared(&As[b][lrow * 20 + lchunk * 4]);
        sA1[b] = (uint32_t)__cvta_generic_to_shared(&As[b][(lrow + 64) * 20 + lchunk * 4]);
        sB0[b] = (uint32_t)__cvta_generic_to_shared(&Bs[b][lrow * 20 + lchunk * 4]);
        sB1[b] = (uint32_t)__cvta_generic_to_shared(&Bs[b][(lrow + 64) * 20 + lchunk * 4]);
    }

    float acc[2][8][4] = {};

    int NT = K >> 5;
    CP_ASYNC16(sA0[0], gA0);
    CP_ASYNC16(sA1[0], gA1);
    CP_ASYNC16(sB0[0], gB0);
    CP_ASYNC16(sB1[0], gB1);
    asm volatile("cp.async.commit_group;\n" ::: "memory");

    for (int it = 0; it < NT; it++) {
        int buf = it & 1;
        if (it + 1 < NT) {
            size_t ko = (size_t)(it + 1) << 5;
            CP_ASYNC16(sA0[buf ^ 1], gA0 + ko);
            CP_ASYNC16(sA1[buf ^ 1], gA1 + ko);
            CP_ASYNC16(sB0[buf ^ 1], gB0 + ko);
            CP_ASYNC16(sB1[buf ^ 1], gB1 + ko);
            asm volatile("cp.async.commit_group;\n" ::: "memory");
            asm volatile("cp.async.wait_group 1;\n" ::: "memory");
        } else {
            asm volatile("cp.async.wait_group 0;\n" ::: "memory");
        }
        __syncthreads();

#pragma unroll
        for (int s = 0; s < 2; s++) {
            uint32_t a[2][4], b[8][2];
#pragma unroll
            for (int mi = 0; mi < 2; mi++) {
                int r = (wm * 32 + mi * 16 + g) * 20 + s * 8 + tq;
                a[mi][0] = As[buf][r];
                a[mi][1] = As[buf][r + 8 * 20];
                a[mi][2] = As[buf][r + 4];
                a[mi][3] = As[buf][r + 8 * 20 + 4];
            }
#pragma unroll
            for (int ni = 0; ni < 8; ni++) {
                int r = (wn * 64 + ni * 8 + g) * 20 + s * 8 + tq;
                b[ni][0] = Bs[buf][r];
                b[ni][1] = Bs[buf][r + 4];
            }
#pragma unroll
            for (int mi = 0; mi < 2; mi++)
#pragma unroll
                for (int ni = 0; ni < 8; ni++)
                    MMA16816(acc[mi][ni], a[mi], b[ni]);
        }
        __syncthreads();
    }

#pragma unroll
    for (int mi = 0; mi < 2; mi++) {
#pragma unroll
        for (int ni = 0; ni < 8; ni++) {
            int row = bm + wm * 32 + mi * 16 + g;
            int col = bn + wn * 64 + ni * 8 + tq * 2;
            __nv_bfloat162* p0 = (__nv_bfloat162*)&C[(size_t)row * N + col];
            __nv_bfloat162* p1 = (__nv_bfloat162*)&C[(size_t)(row + 8) * N + col];
            *p0 = __float22bfloat162_rn(make_float2(acc[mi][ni][0], acc[mi][ni][1]));
            *p1 = __float22bfloat162_rn(make_float2(acc[mi][ni][2], acc[mi][ni][3]));
        }
    }
}

// ---------------- fused delta: R (+)= Xf@Pw^T + Xa@Aw^T (bf16 in, fp32 accum) ----
__global__ __launch_bounds__(128) void k_delta(const bf16* __restrict__ Xf, const bf16* __restrict__ Xa,
                                               const float* __restrict__ Pw, const float* __restrict__ Aw,
                                               float* __restrict__ R, int accumulate) {
    __shared__ float xsf[16][68], xsa[16][68];
    __shared__ float wsp[16][132], wsa[16][132];
    int t = threadIdx.x;
    int r0 = blockIdx.x * 64;
    int ty = t >> 4, tx = t & 15;
    float acc[8][8] = {};
    for (int kb = 0; kb < 128; kb += 16) {
        for (int idx = t; idx < 64 * 16; idx += 128) {
            int r = idx >> 4, c = idx & 15;
            xsf[c][r] = __bfloat162float(Xf[(size_t)(r0 + r) * 128 + kb + c]);
            xsa[c][r] = __bfloat162float(Xa[(size_t)(r0 + r) * 128 + kb + c]);
        }
        for (int idx = t; idx < 128 * 16; idx += 128) {
            int d = idx >> 4, c = idx & 15;
            wsp[c][d] = Pw[d * 128 + kb + c];
            wsa[c][d] = Aw[d * 128 + kb + c];
        }
        __syncthreads();
#pragma unroll
        for (int c = 0; c < 16; c++) {
            float xf[8], xa[8], pw[8], aw[8];
            *(float4*)&xf[0] = *(const float4*)&xsf[c][ty * 8];
            *(float4*)&xf[4] = *(const float4*)&xsf[c][ty * 8 + 4];
            *(float4*)&xa[0] = *(const float4*)&xsa[c][ty * 8];
            *(float4*)&xa[4] = *(const float4*)&xsa[c][ty * 8 + 4];
            *(float4*)&pw[0] = *(const float4*)&wsp[c][tx * 8];
            *(float4*)&pw[4] = *(const float4*)&wsp[c][tx * 8 + 4];
            *(float4*)&aw[0] = *(const float4*)&wsa[c][tx * 8];
            *(float4*)&aw[4] = *(const float4*)&wsa[c][tx * 8 + 4];
#pragma unroll
            for (int i = 0; i < 8; i++)
#pragma unroll
                for (int j = 0; j < 8; j++)
                    acc[i][j] += xf[i] * pw[j] + xa[i] * aw[j];
        }
        __syncthreads();
    }
#pragma unroll
    for (int i = 0; i < 8; i++) {
        size_t o = (size_t)(r0 + ty * 8 + i) * 128 + tx * 8;
        if (accumulate) {
#pragma unroll
            for (int j = 0; j < 8; j++) R[o + j] += acc[i][j];
        } else {
            *(float4*)&R[o]     = make_float4(acc[i][0], acc[i][1], acc[i][2], acc[i][3]);
            *(float4*)&R[o + 4] = make_float4(acc[i][4], acc[i][5], acc[i][6], acc[i][7]);
        }
    }
}

// ---------------- final: out = LN(x + sigmoid(alpha)*res) ----------------
__global__ void k_ln(const float* __restrict__ x, const float* __restrict__ gamma,
                     const float* __restrict__ beta, const float* __restrict__ alpha,
                     float* __restrict__ out) {
    int row = blockIdx.x * 8 + (threadIdx.x >> 5);
    int lane = threadIdx.x & 31;
    float gate = 1.0f / (1.0f + expf(-alpha[0]));
    size_t base = (size_t)row * CDIM;
    float h[4];
    float s = 0.f;
#pragma unroll
    for (int u = 0; u < 4; u++) {
        int c = lane + u * 32;
        h[u] = x[base + c] + gate * g_res[base + c];
        s += h[u];
    }
#pragma unroll
    for (int o = 16; o; o >>= 1) s += __shfl_xor_sync(0xffffffffu, s, o);
    float mu = s * (1.0f / CDIM);
    float v = 0.f;
#pragma unroll
    for (int u = 0; u < 4; u++) { float d = h[u] - mu; v += d * d; }
#pragma unroll
    for (int o = 16; o; o >>= 1) v += __shfl_xor_sync(0xffffffffu, v, o);
    float rs = rsqrtf(v * (1.0f / CDIM) + LN_EPS);
#pragma unroll
    for (int u = 0; u < 4; u++) {
        int c = lane + u * 32;
        out[base + c] = (h[u] - mu) * rs * gamma[c] + beta[c];
    }
}

// ---------------- host orchestration ----------------
extern "C" void kernel_launch(void* const* d_in, const int* in_sizes, int n_in,
                              void* d_out, int out_size) {
    const float* x     = (const float*)d_in[0];
    const float* prior = (const float*)d_in[1];
    const float* W1    = (const float*)d_in[2];
    const float* W2    = (const float*)d_in[3];
    const float* W3    = (const float*)d_in[4];
    const float* Pfw   = (const float*)d_in[5];
    const float* Awt   = (const float*)d_in[6];
    const float* gamma = (const float*)d_in[7];
    const float* beta  = (const float*)d_in[8];
    const float* alpha = (const float*)d_in[9];
    float* out = (float*)d_out;

    bf16 *RfB, *attnB, *xT, *Xf1, *Xa1, *Xf2, *Xa2, *Xf1T, *Xa1T;
    float *res;
    cudaGetSymbolAddress((void**)&RfB,   g_RfB);
    cudaGetSymbolAddress((void**)&attnB, g_attnB);
    cudaGetSymbolAddress((void**)&xT,    g_xT);
    cudaGetSymbolAddress((void**)&Xf1,   g_Xf1);
    cudaGetSymbolAddress((void**)&Xa1,   g_Xa1);
    cudaGetSymbolAddress((void**)&Xf2,   g_Xf2);
    cudaGetSymbolAddress((void**)&Xa2,   g_Xa2);
    cudaGetSymbolAddress((void**)&Xf1T,  g_Xf1T);
    cudaGetSymbolAddress((void**)&Xa1T,  g_Xa1T);
    cudaGetSymbolAddress((void**)&res,   g_res);

    k_rowsum<<<NP, 256>>>(prior);
    k_scaleRf<<<4096, 256>>>(prior);
    k_transpose_f2b<<<dim3(NCC / 32, NP / 32), dim3(32, 8)>>>(x, xT, NP, NCC);

    for (int step = 0; step < 2; step++) {
        if (step == 0) k_pool_f<<<NP, CDIM>>>(x);
        else           k_pool_b<<<NP, CDIM>>>(Xa1);
        k_e1e3<<<NP, DDIM>>>(W1, W3);
        k_f<<<NP, DDIM>>>(W2);
        k_logits<<<dim3(32, 32), 256>>>();
        k_softmax<<<NP, 256>>>();
        k_topp<<<NP, 1024>>>();
        k_mask<<<4096, 256>>>();

        const bf16* BT_f = step ? (const bf16*)Xf1T : (const bf16*)xT;
        const bf16* BT_a = step ? (const bf16*)Xa1T : (const bf16*)xT;
        bf16* Xf_out = step ? Xf2 : Xf1;
        bf16* Xa_out = step ? Xa2 : Xa1;

        k_gemm_bf16<<<dim3(NCC / 128, NP / 128), 256>>>(RfB,   BT_f, Xf_out, NP, NCC, NP);
        k_gemm_bf16<<<dim3(NCC / 128, NP / 128), 256>>>(attnB, BT_a, Xa_out, NP, NCC, NP);

        k_delta<<<2048, 128>>>(Xf_out, Xa_out,
                               Pfw + (size_t)step * CDIM * CDIM,
                               Awt + (size_t)step * CDIM * CDIM,
                               res, step);

        if (step == 0) {
            k_transpose_b2b<<<dim3(NCC / 32, NP / 32), dim3(32, 8)>>>(Xf1, Xf1T, NP, NCC);
            k_transpose_b2b<<<dim3(NCC / 32, NP / 32), dim3(32, 8)>>>(Xa1, Xa1T, NP, NCC);
        }
    }

    k_ln<<<(int)(TOT / CDIM / 8), 256>>>(x, gamma, beta, alpha, out);
}

// round 5
// speedup vs baseline: 4.3083x; 1.4293x over previous
#include <cuda_runtime.h>
#include <cuda_bf16.h>
#include <cstdint>

#define NP 2048
#define NC 64
#define CDIM 128
#define DDIM 64
#define NCC (NC*CDIM)              /* 8192 */
#define TOT ((size_t)NP*NCC)       /* 16777216 */
#define P_TOPP 0.9f
#define LN_EPS 1e-5f

typedef __nv_bfloat16 bf16;

// ---------------- scratch (device globals; allowed) ----------------
__device__ __align__(128) bf16  g_RfB[(size_t)NP*NP];
__device__ __align__(128) float g_attn[(size_t)NP*NP];     // raw logits
__device__ __align__(128) bf16  g_attnB[(size_t)NP*NP];    // masked+renormed bf16
__device__ float g_rowinv[NP];
__device__ float g_pooled[NP*CDIM];
__device__ float g_e1[NP*DDIM];
__device__ float g_e3[NP*DDIM];
__device__ float g_fm[NP*DDIM];
__device__ __align__(128) bf16 g_xT[TOT];
__device__ __align__(128) bf16 g_Xf1[TOT];
__device__ __align__(128) bf16 g_Xa1[TOT];
__device__ __align__(128) bf16 g_Xf2[TOT];
__device__ __align__(128) bf16 g_Xa2[TOT];
__device__ __align__(128) bf16 g_Xf1T[TOT];
__device__ __align__(128) bf16 g_Xa1T[TOT];
__device__ __align__(128) float g_res[TOT];

// ---------------- prior row-normalization ----------------
__global__ void k_rowsum(const float* __restrict__ prior) {
    __shared__ float red[256];
    int row = blockIdx.x, t = threadIdx.x;
    const float* p = prior + (size_t)row * NP;
    float s = 0.f;
    for (int j = t; j < NP; j += 256) s += p[j];
    red[t] = s; __syncthreads();
    for (int o = 128; o; o >>= 1) { if (t < o) red[t] += red[t + o]; __syncthreads(); }
    if (t == 0) g_rowinv[row] = 1.0f / fmaxf(red[0], 1e-12f);
}

__global__ void k_scaleRf(const float* __restrict__ prior) {
    size_t idx = (size_t)blockIdx.x * blockDim.x + threadIdx.x;
    size_t stride = (size_t)gridDim.x * blockDim.x;
    for (size_t i = idx; i < (size_t)NP * NP; i += stride)
        g_RfB[i] = __float2bfloat16(prior[i] * g_rowinv[i >> 11]);
}

// ---------------- transposes ----------------
__global__ void k_transpose_f2b(const float* __restrict__ in, bf16* __restrict__ out,
                                int R, int Ccols) {
    __shared__ float tile[32][33];
    int bx = blockIdx.x * 32, by = blockIdx.y * 32;
    int tx = threadIdx.x, ty = threadIdx.y;   // 32 x 8
#pragma unroll
    for (int j = 0; j < 32; j += 8)
        tile[ty + j][tx] = in[(size_t)(by + ty + j) * Ccols + bx + tx];
    __syncthreads();
#pragma unroll
    for (int j = 0; j < 32; j += 8)
        out[(size_t)(bx + ty + j) * R + by + tx] = __float2bfloat16(tile[tx][ty + j]);
}

__global__ void k_transpose_b2b(const bf16* __restrict__ in, bf16* __restrict__ out,
                                int R, int Ccols) {
    __shared__ float tile[32][33];
    int bx = blockIdx.x * 32, by = blockIdx.y * 32;
    int tx = threadIdx.x, ty = threadIdx.y;
#pragma unroll
    for (int j = 0; j < 32; j += 8)
        tile[ty + j][tx] = __bfloat162float(in[(size_t)(by + ty + j) * Ccols + bx + tx]);
    __syncthreads();
#pragma unroll
    for (int j = 0; j < 32; j += 8)
        out[(size_t)(bx + ty + j) * R + by + tx] = __float2bfloat16(tile[tx][ty + j]);
}

// ---------------- mean pool over protein axis ----------------
__global__ void k_pool_f(const float* __restrict__ X) {
    int i = blockIdx.x, c = threadIdx.x;
    const float* p = X + (size_t)i * NCC + c;
    float s = 0.f;
#pragma unroll
    for (int k = 0; k < NC; k++) s += p[k * CDIM];
    g_pooled[i * CDIM + c] = s * (1.0f / NC);
}

__global__ void k_pool_b(const bf16* __restrict__ X) {
    int i = blockIdx.x, c = threadIdx.x;
    const bf16* p = X + (size_t)i * NCC + c;
    float s = 0.f;
#pragma unroll
    for (int k = 0; k < NC; k++) s += __bfloat162float(p[k * CDIM]);
    g_pooled[i * CDIM + c] = s * (1.0f / NC);
}

// ---------------- small projections ----------------
__global__ void k_e1e3(const float* __restrict__ W1, const float* __restrict__ W3) {
    int i = blockIdx.x, d = threadIdx.x;  // 64 threads
    __shared__ float p[CDIM];
    p[d] = g_pooled[i * CDIM + d];
    p[d + 64] = g_pooled[i * CDIM + d + 64];
    __syncthreads();
    float s1 = 0.f, s3 = 0.f;
#pragma unroll 4
    for (int c = 0; c < CDIM; c++) {
        float pc = p[c];
        s1 += pc * W1[d * CDIM + c];
        s3 += pc * W3[d * CDIM + c];
    }
    g_e1[i * DDIM + d] = s1;
    g_e3[i * DDIM + d] = s3;
}

__global__ void k_f(const float* __restrict__ W2) {
    int i = blockIdx.x, d = threadIdx.x;  // 64 threads
    __shared__ float e[DDIM];
    e[d] = g_e1[i * DDIM + d];
    __syncthreads();
    float s = 0.f;
#pragma unroll 4
    for (int k = 0; k < DDIM; k++) s += e[k] * W2[d * DDIM + k];
    g_fm[i * DDIM + d] = s;
}

// logits[i,n] = sum_k f[i,k]*e3[n,k]
__global__ __launch_bounds__(256) void k_logits() {
    __shared__ float Fs[64][65];
    __shared__ float Es[64][65];
    int bm = blockIdx.y * 64, bn = blockIdx.x * 64;
    int t = threadIdx.x;
    for (int idx = t; idx < 64 * 64; idx += 256) {
        int r = idx >> 6, c = idx & 63;
        Fs[r][c] = g_fm[(bm + r) * 64 + c];
        Es[r][c] = g_e3[(bn + r) * 64 + c];
    }
    __syncthreads();
    int tx = t & 15, ty = t >> 4;
    float acc[4][4] = {};
    for (int k = 0; k < 64; k++) {
        float a[4], b[4];
#pragma unroll
        for (int r = 0; r < 4; r++) { a[r] = Fs[ty * 4 + r][k]; b[r] = Es[tx * 4 + r][k]; }
#pragma unroll
        for (int i = 0; i < 4; i++)
#pragma unroll
            for (int j = 0; j < 4; j++) acc[i][j] += a[i] * b[j];
    }
#pragma unroll
    for (int i = 0; i < 4; i++)
#pragma unroll
        for (int j = 0; j < 4; j++)
            g_attn[(size_t)(bm + ty * 4 + i) * NP + bn + tx * 4 + j] = acc[i][j];
}

// ---------------- fused softmax + top-p (bit-pattern bisection) + mask ----------------
__device__ __forceinline__ float blkSum(float v, float* red) {
#pragma unroll
    for (int o = 16; o; o >>= 1) v += __shfl_xor_sync(0xffffffffu, v, o);
    int warp = threadIdx.x >> 5, lane = threadIdx.x & 31;
    __syncthreads();
    if (lane == 0) red[warp] = v;
    __syncthreads();
    if (threadIdx.x == 0) {
        float s = 0.f;
#pragma unroll
        for (int i = 0; i < 8; i++) s += red[i];
        red[0] = s;
    }
    __syncthreads();
    return red[0];
}

__global__ __launch_bounds__(256) void k_softtopp() {
    __shared__ float red[8];
    int row = blockIdx.x, t = threadIdx.x;
    const float* a = g_attn + (size_t)row * NP;
    float v[8];
#pragma unroll
    for (int u = 0; u < 8; u++) v[u] = a[t + u * 256];
    // block max
    float m = v[0];
#pragma unroll
    for (int u = 1; u < 8; u++) m = fmaxf(m, v[u]);
#pragma unroll
    for (int o = 16; o; o >>= 1) m = fmaxf(m, __shfl_xor_sync(0xffffffffu, m, o));
    {
        int warp = t >> 5, lane = t & 31;
        if (lane == 0) red[warp] = m;
        __syncthreads();
        if (t == 0) {
            float mm = red[0];
#pragma unroll
            for (int i = 1; i < 8; i++) mm = fmaxf(mm, red[i]);
            red[0] = mm;
        }
        __syncthreads();
        m = red[0];
    }
    // exp + total
    float e[8];
    float tot = 0.f;
#pragma unroll
    for (int u = 0; u < 8; u++) { e[u] = __expf(v[u] - m); tot += e[u]; }
    tot = blkSum(tot, red);
    float target = P_TOPP * tot;
    // bisection on positive-float bit patterns: largest t with F(t) >= target
    unsigned lo = 0u, hi = 0x3F800000u;  // [0, 1.0] — max exp value is exactly 1
    while (lo < hi) {
        unsigned mid = lo + ((hi - lo + 1) >> 1);
        float tm = __uint_as_float(mid);
        float p = 0.f;
#pragma unroll
        for (int u = 0; u < 8; u++) p += (e[u] >= tm) ? e[u] : 0.f;
        p = blkSum(p, red);
        if (p >= target) lo = mid; else hi = mid - 1;
    }
    float thr = __uint_as_float(lo);
    float F = 0.f;
#pragma unroll
    for (int u = 0; u < 8; u++) F += (e[u] >= thr) ? e[u] : 0.f;
    F = blkSum(F, red);
    float inv = 1.0f / fmaxf(F, 1e-30f);
    bf16* o = g_attnB + (size_t)row * NP;
#pragma unroll
    for (int u = 0; u < 8; u++)
        o[t + u * 256] = __float2bfloat16((e[u] >= thr) ? e[u] * inv : 0.0f);
}

// ---------------- bf16 tensor-core GEMM (unchanged, validated) ----------------
#define CP_ASYNC16(dst_u32, src_ptr) \
    asm volatile("cp.async.cg.shared.global [%0], [%1], 16;\n" :: "r"(dst_u32), "l"(src_ptr))
#define MMA16816(d, a, b) \
    asm volatile("mma.sync.aligned.m16n8k16.row.col.f32.bf16.bf16.f32 " \
                 "{%0,%1,%2,%3},{%4,%5,%6,%7},{%8,%9},{%0,%1,%2,%3};" \
                 : "+f"(d[0]), "+f"(d[1]), "+f"(d[2]), "+f"(d[3]) \
                 : "r"(a[0]), "r"(a[1]), "r"(a[2]), "r"(a[3]), "r"(b[0]), "r"(b[1]))

__global__ __launch_bounds__(256) void k_gemm_bf16(
    const bf16* __restrict__ A, const bf16* __restrict__ BT, bf16* __restrict__ C,
    int M, int N, int K)
{
    __shared__ uint32_t As[2][128 * 20];
    __shared__ uint32_t Bs[2][128 * 20];
    int t = threadIdx.x;
    int bm = blockIdx.y << 7, bn = blockIdx.x << 7;
    int warp = t >> 5, lane = t & 31;
    int wm = warp & 3, wn = warp >> 2;
    int g = lane >> 2, tq = lane & 3;

    int lrow = t >> 2, lchunk = t & 3;
    const bf16* gA0 = A  + (size_t)(bm + lrow) * K      + lchunk * 8;
    const bf16* gA1 = A  + (size_t)(bm + lrow + 64) * K + lchunk * 8;
    const bf16* gB0 = BT + (size_t)(bn + lrow) * K      + lchunk * 8;
    const bf16* gB1 = BT + (size_t)(bn + lrow + 64) * K + lchunk * 8;
    uint32_t sA0[2], sA1[2], sB0[2], sB1[2];
#pragma unroll
    for (int b = 0; b < 2; b++) {
        sA0[b] = (uint32_t)__cvta_generic_to_shared(&As[b][lrow * 20 + lchunk * 4]);
        sA1[b] = (uint32_t)__cvta_generic_to_shared(&As[b][(lrow + 64) * 20 + lchunk * 4]);
        sB0[b] = (uint32_t)__cvta_generic_to_shared(&Bs[b][lrow * 20 + lchunk * 4]);
        sB1[b] = (uint32_t)__cvta_generic_to_shared(&Bs[b][(lrow + 64) * 20 + lchunk * 4]);
    }

    float acc[2][8][4] = {};

    int NT = K >> 5;
    CP_ASYNC16(sA0[0], gA0);
    CP_ASYNC16(sA1[0], gA1);
    CP_ASYNC16(sB0[0], gB0);
    CP_ASYNC16(sB1[0], gB1);
    asm volatile("cp.async.commit_group;\n" ::: "memory");

    for (int it = 0; it < NT; it++) {
        int buf = it & 1;
        if (it + 1 < NT) {
            size_t ko = (size_t)(it + 1) << 5;
            CP_ASYNC16(sA0[buf ^ 1], gA0 + ko);
            CP_ASYNC16(sA1[buf ^ 1], gA1 + ko);
            CP_ASYNC16(sB0[buf ^ 1], gB0 + ko);
            CP_ASYNC16(sB1[buf ^ 1], gB1 + ko);
            asm volatile("cp.async.commit_group;\n" ::: "memory");
            asm volatile("cp.async.wait_group 1;\n" ::: "memory");
        } else {
            asm volatile("cp.async.wait_group 0;\n" ::: "memory");
        }
        __syncthreads();

#pragma unroll
        for (int s = 0; s < 2; s++) {
            uint32_t a[2][4], b[8][2];
#pragma unroll
            for (int mi = 0; mi < 2; mi++) {
                int r = (wm * 32 + mi * 16 + g) * 20 + s * 8 + tq;
                a[mi][0] = As[buf][r];
                a[mi][1] = As[buf][r + 8 * 20];
                a[mi][2] = As[buf][r + 4];
                a[mi][3] = As[buf][r + 8 * 20 + 4];
            }
#pragma unroll
            for (int ni = 0; ni < 8; ni++) {
                int r = (wn * 64 + ni * 8 + g) * 20 + s * 8 + tq;
                b[ni][0] = Bs[buf][r];
                b[ni][1] = Bs[buf][r + 4];
            }
#pragma unroll
            for (int mi = 0; mi < 2; mi++)
#pragma unroll
                for (int ni = 0; ni < 8; ni++)
                    MMA16816(acc[mi][ni], a[mi], b[ni]);
        }
        __syncthreads();
    }

#pragma unroll
    for (int mi = 0; mi < 2; mi++) {
#pragma unroll
        for (int ni = 0; ni < 8; ni++) {
            int row = bm + wm * 32 + mi * 16 + g;
            int col = bn + wn * 64 + ni * 8 + tq * 2;
            __nv_bfloat162* p0 = (__nv_bfloat162*)&C[(size_t)row * N + col];
            __nv_bfloat162* p1 = (__nv_bfloat162*)&C[(size_t)(row + 8) * N + col];
            *p0 = __float22bfloat162_rn(make_float2(acc[mi][ni][0], acc[mi][ni][1]));
            *p1 = __float22bfloat162_rn(make_float2(acc[mi][ni][2], acc[mi][ni][3]));
        }
    }
}

// ---------------- tensor-core delta: res (+)= Xf@Pw^T + Xa@Aw^T, fp32 accum ----------
// per block: 128 rows x 128 cols, K=128. dynamic smem 160KB:
// [Pw 4x(128x20)] [Aw ...] [Xf ...] [Xa ...] (chunks of K=32, stride-20 words)
__global__ __launch_bounds__(256) void k_delta_mma(
    const bf16* __restrict__ Xf, const bf16* __restrict__ Xa,
    const float* __restrict__ Pw, const float* __restrict__ Aw,
    float* __restrict__ R, int accumulate)
{
    extern __shared__ uint32_t sm[];
    uint32_t* sPw = sm;
    uint32_t* sAw = sm + 10240;
    uint32_t* sXf = sm + 20480;
    uint32_t* sXa = sm + 30720;
    int t = threadIdx.x;
    size_t r0 = (size_t)blockIdx.x * 128;

    // weights fp32 -> bf16 into chunked layout
    for (int idx = t; idx < 128 * 64; idx += 256) {
        int n = idx >> 6, w = idx & 63;
        int c = w >> 4, ww = w & 15;
        float2 pv = *(const float2*)&Pw[n * 128 + w * 2];
        float2 av = *(const float2*)&Aw[n * 128 + w * 2];
        __nv_bfloat162 pb = __float22bfloat162_rn(pv);
        __nv_bfloat162 ab = __float22bfloat162_rn(av);
        sPw[c * 2560 + n * 20 + ww] = *(uint32_t*)&pb;
        sAw[c * 2560 + n * 20 + ww] = *(uint32_t*)&ab;
    }
    // X tiles (already bf16)
    const uint32_t* xf32 = (const uint32_t*)(Xf + r0 * 128);
    const uint32_t* xa32 = (const uint32_t*)(Xa + r0 * 128);
    for (int idx = t; idx < 128 * 64; idx += 256) {
        int n = idx >> 6, w = idx & 63;
        int c = w >> 4, ww = w & 15;
        sXf[c * 2560 + n * 20 + ww] = xf32[n * 64 + w];
        sXa[c * 2560 + n * 20 + ww] = xa32[n * 64 + w];
    }
    __syncthreads();

    int warp = t >> 5, lane = t & 31;
    int wm = warp & 3, wn = warp >> 2;
    int g = lane >> 2, tq = lane & 3;
    float acc[2][8][4] = {};

#pragma unroll
    for (int c = 0; c < 4; c++) {
        const uint32_t* cf = sXf + c * 2560;
        const uint32_t* ca = sXa + c * 2560;
        const uint32_t* cp = sPw + c * 2560;
        const uint32_t* cw = sAw + c * 2560;
#pragma unroll
        for (int s = 0; s < 2; s++) {
            uint32_t af[2][4], aa[2][4], bp[8][2], ba[8][2];
#pragma unroll
            for (int mi = 0; mi < 2; mi++) {
                int r = (wm * 32 + mi * 16 + g) * 20 + s * 8 + tq;
                af[mi][0] = cf[r];       af[mi][1] = cf[r + 160];
                af[mi][2] = cf[r + 4];   af[mi][3] = cf[r + 164];
                aa[mi][0] = ca[r];       aa[mi][1] = ca[r + 160];
                aa[mi][2] = ca[r + 4];   aa[mi][3] = ca[r + 164];
            }
#pragma unroll
            for (int ni = 0; ni < 8; ni++) {
                int rb = (wn * 64 + ni * 8 + g) * 20 + s * 8 + tq;
                bp[ni][0] = cp[rb]; bp[ni][1] = cp[rb + 4];
                ba[ni][0] = cw[rb]; ba[ni][1] = cw[rb + 4];
            }
#pragma unroll
            for (int mi = 0; mi < 2; mi++)
#pragma unroll
                for (int ni = 0; ni < 8; ni++) {
                    MMA16816(acc[mi][ni], af[mi], bp[ni]);
                    MMA16816(acc[mi][ni], aa[mi], ba[ni]);
                }
        }
    }

#pragma unroll
    for (int mi = 0; mi < 2; mi++) {
#pragma unroll
        for (int ni = 0; ni < 8; ni++) {
            int row = wm * 32 + mi * 16 + g;
            int col = wn * 64 + ni * 8 + tq * 2;
            float* p0 = &R[(r0 + row) * 128 + col];
            float* p1 = &R[(r0 + row + 8) * 128 + col];
            if (accumulate) {
                p0[0] += acc[mi][ni][0]; p0[1] += acc[mi][ni][1];
                p1[0] += acc[mi][ni][2]; p1[1] += acc[mi][ni][3];
            } else {
                *(float2*)p0 = make_float2(acc[mi][ni][0], acc[mi][ni][1]);
                *(float2*)p1 = make_float2(acc[mi][ni][2], acc[mi][ni][3]);
            }
        }
    }
}

// ---------------- final: out = LN(x + sigmoid(alpha)*res) ----------------
__global__ void k_ln(const float* __restrict__ x, const float* __restrict__ gamma,
                     const float* __restrict__ beta, const float* __restrict__ alpha,
                     float* __restrict__ out) {
    int row = blockIdx.x * 8 + (threadIdx.x >> 5);
    int lane = threadIdx.x & 31;
    float gate = 1.0f / (1.0f + expf(-alpha[0]));
    size_t base = (size_t)row * CDIM;
    float h[4];
    float s = 0.f;
#pragma unroll
    for (int u = 0; u < 4; u++) {
        int c = lane + u * 32;
        h[u] = x[base + c] + gate * g_res[base + c];
        s += h[u];
    }
#pragma unroll
    for (int o = 16; o; o >>= 1) s += __shfl_xor_sync(0xffffffffu, s, o);
    float mu = s * (1.0f / CDIM);
    float v = 0.f;
#pragma unroll
    for (int u = 0; u < 4; u++) { float d = h[u] - mu; v += d * d; }
#pragma unroll
    for (int o = 16; o; o >>= 1) v += __shfl_xor_sync(0xffffffffu, v, o);
    float rs = rsqrtf(v * (1.0f / CDIM) + LN_EPS);
#pragma unroll
    for (int u = 0; u < 4; u++) {
        int c = lane + u * 32;
        out[base + c] = (h[u] - mu) * rs * gamma[c] + beta[c];
    }
}

// ---------------- host orchestration ----------------
extern "C" void kernel_launch(void* const* d_in, const int* in_sizes, int n_in,
                              void* d_out, int out_size) {
    const float* x     = (const float*)d_in[0];
    const float* prior = (const float*)d_in[1];
    const float* W1    = (const float*)d_in[2];
    const float* W2    = (const float*)d_in[3];
    const float* W3    = (const float*)d_in[4];
    const float* Pfw   = (const float*)d_in[5];
    const float* Awt   = (const float*)d_in[6];
    const float* gamma = (const float*)d_in[7];
    const float* beta  = (const float*)d_in[8];
    const float* alpha = (const float*)d_in[9];
    float* out = (float*)d_out;

    bf16 *RfB, *attnB, *xT, *Xf1, *Xa1, *Xf2, *Xa2, *Xf1T, *Xa1T;
    float *res;
    cudaGetSymbolAddress((void**)&RfB,   g_RfB);
    cudaGetSymbolAddress((void**)&attnB, g_attnB);
    cudaGetSymbolAddress((void**)&xT,    g_xT);
    cudaGetSymbolAddress((void**)&Xf1,   g_Xf1);
    cudaGetSymbolAddress((void**)&Xa1,   g_Xa1);
    cudaGetSymbolAddress((void**)&Xf2,   g_Xf2);
    cudaGetSymbolAddress((void**)&Xa2,   g_Xa2);
    cudaGetSymbolAddress((void**)&Xf1T,  g_Xf1T);
    cudaGetSymbolAddress((void**)&Xa1T,  g_Xa1T);
    cudaGetSymbolAddress((void**)&res,   g_res);

    static bool attr_done = false;
    if (!attr_done) {
        cudaFuncSetAttribute(k_delta_mma, cudaFuncAttributeMaxDynamicSharedMemorySize, 163840);
        attr_done = true;
    }

    k_rowsum<<<NP, 256>>>(prior);
    k_scaleRf<<<4096, 256>>>(prior);
    k_transpose_f2b<<<dim3(NCC / 32, NP / 32), dim3(32, 8)>>>(x, xT, NP, NCC);

    for (int step = 0; step < 2; step++) {
        if (step == 0) k_pool_f<<<NP, CDIM>>>(x);
        else           k_pool_b<<<NP, CDIM>>>(Xa1);
        k_e1e3<<<NP, DDIM>>>(W1, W3);
        k_f<<<NP, DDIM>>>(W2);
        k_logits<<<dim3(32, 32), 256>>>();
        k_softtopp<<<NP, 256>>>();

        const bf16* BT_f = step ? (const bf16*)Xf1T : (const bf16*)xT;
        const bf16* BT_a = step ? (const bf16*)Xa1T : (const bf16*)xT;
        bf16* Xf_out = step ? Xf2 : Xf1;
        bf16* Xa_out = step ? Xa2 : Xa1;

        k_gemm_bf16<<<dim3(NCC / 128, NP / 128), 256>>>(RfB,   BT_f, Xf_out, NP, NCC, NP);
        k_gemm_bf16<<<dim3(NCC / 128, NP / 128), 256>>>(attnB, BT_a, Xa_out, NP, NCC, NP);

        k_delta_mma<<<1024, 256, 163840>>>(Xf_out, Xa_out,
                               Pfw + (size_t)step * CDIM * CDIM,
                               Awt + (size_t)step * CDIM * CDIM,
                               res, step);

        if (step == 0) {
            k_transpose_b2b<<<dim3(NCC / 32, NP / 32), dim3(32, 8)>>>(Xf1, Xf1T, NP, NCC);
            k_transpose_b2b<<<dim3(NCC / 32, NP / 32), dim3(32, 8)>>>(Xa1, Xa1T, NP, NCC);
        }
    }

    k_ln<<<(int)(TOT / CDIM / 8), 256>>>(x, gamma, beta, alpha, out);
}

// round 8
// speedup vs baseline: 4.4982x; 1.0441x over previous
#include <cuda_runtime.h>
#include <cuda_bf16.h>
#include <cstdint>

#define NP 2048
#define NC 64
#define CDIM 128
#define DDIM 64
#define NCC (NC*CDIM)              /* 8192 */
#define TOT ((size_t)NP*NCC)       /* 16777216 */
#define P_TOPP 0.9f
#define LN_EPS 1e-5f

typedef __nv_bfloat16 bf16;

// ---------------- scratch (device globals; allowed) ----------------
__device__ __align__(128) bf16  g_RfB[(size_t)NP*NP];
__device__ __align__(128) float g_attn[(size_t)NP*NP];     // raw logits
__device__ __align__(128) bf16  g_attnB[(size_t)NP*NP];    // masked+renormed bf16
__device__ float g_rowinv[NP];
__device__ float g_pooled[NP*CDIM];
__device__ float g_e1[NP*DDIM];
__device__ float g_e3[NP*DDIM];
__device__ float g_fm[NP*DDIM];
__device__ __align__(128) bf16 g_xT[TOT];
__device__ __align__(128) bf16 g_Xf1[TOT];
__device__ __align__(128) bf16 g_Xa1[TOT];
__device__ __align__(128) bf16 g_Xf2[TOT];
__device__ __align__(128) bf16 g_Xa2[TOT];
__device__ __align__(128) bf16 g_Xf1T[TOT];
__device__ __align__(128) bf16 g_Xa1T[TOT];
__device__ __align__(128) float g_res[TOT];

// ---------------- prior row-normalization ----------------
__global__ void k_rowsum(const float* __restrict__ prior) {
    __shared__ float red[256];
    int row = blockIdx.x, t = threadIdx.x;
    const float* p = prior + (size_t)row * NP;
    float s = 0.f;
    for (int j = t; j < NP; j += 256) s += p[j];
    red[t] = s; __syncthreads();
    for (int o = 128; o; o >>= 1) { if (t < o) red[t] += red[t + o]; __syncthreads(); }
    if (t == 0) g_rowinv[row] = 1.0f / fmaxf(red[0], 1e-12f);
}

__global__ void k_scaleRf(const float* __restrict__ prior) {
    size_t idx = (size_t)blockIdx.x * blockDim.x + threadIdx.x;
    size_t stride = (size_t)gridDim.x * blockDim.x;
    for (size_t i = idx; i < (size_t)NP * NP; i += stride)
        g_RfB[i] = __float2bfloat16(prior[i] * g_rowinv[i >> 11]);
}

// ---------------- transposes ----------------
__global__ void k_transpose_f2b(const float* __restrict__ in, bf16* __restrict__ out,
                                int R, int Ccols) {
    __shared__ float tile[32][33];
    int bx = blockIdx.x * 32, by = blockIdx.y * 32;
    int tx = threadIdx.x, ty = threadIdx.y;   // 32 x 8
#pragma unroll
    for (int j = 0; j < 32; j += 8)
        tile[ty + j][tx] = in[(size_t)(by + ty + j) * Ccols + bx + tx];
    __syncthreads();
#pragma unroll
    for (int j = 0; j < 32; j += 8)
        out[(size_t)(bx + ty + j) * R + by + tx] = __float2bfloat16(tile[tx][ty + j]);
}

__global__ void k_transpose_b2b(const bf16* __restrict__ in, bf16* __restrict__ out,
                                int R, int Ccols) {
    __shared__ float tile[32][33];
    int bx = blockIdx.x * 32, by = blockIdx.y * 32;
    int tx = threadIdx.x, ty = threadIdx.y;
#pragma unroll
    for (int j = 0; j < 32; j += 8)
        tile[ty + j][tx] = __bfloat162float(in[(size_t)(by + ty + j) * Ccols + bx + tx]);
    __syncthreads();
#pragma unroll
    for (int j = 0; j < 32; j += 8)
        out[(size_t)(bx + ty + j) * R + by + tx] = __float2bfloat16(tile[tx][ty + j]);
}

// ---------------- mean pool over protein axis ----------------
__global__ void k_pool_f(const float* __restrict__ X) {
    int i = blockIdx.x, c = threadIdx.x;
    const float* p = X + (size_t)i * NCC + c;
    float s = 0.f;
#pragma unroll
    for (int k = 0; k < NC; k++) s += p[k * CDIM];
    g_pooled[i * CDIM + c] = s * (1.0f / NC);
}

__global__ void k_pool_b(const bf16* __restrict__ X) {
    int i = blockIdx.x, c = threadIdx.x;
    const bf16* p = X + (size_t)i * NCC + c;
    float s = 0.f;
#pragma unroll
    for (int k = 0; k < NC; k++) s += __bfloat162float(p[k * CDIM]);
    g_pooled[i * CDIM + c] = s * (1.0f / NC);
}

// ---------------- small projections ----------------
__global__ void k_e1e3(const float* __restrict__ W1, const float* __restrict__ W3) {
    int i = blockIdx.x, d = threadIdx.x;  // 64 threads
    __shared__ float p[CDIM];
    p[d] = g_pooled[i * CDIM + d];
    p[d + 64] = g_pooled[i * CDIM + d + 64];
    __syncthreads();
    float s1 = 0.f, s3 = 0.f;
#pragma unroll 4
    for (int c = 0; c < CDIM; c++) {
        float pc = p[c];
        s1 += pc * W1[d * CDIM + c];
        s3 += pc * W3[d * CDIM + c];
    }
    g_e1[i * DDIM + d] = s1;
    g_e3[i * DDIM + d] = s3;
}

__global__ void k_f(const float* __restrict__ W2) {
    int i = blockIdx.x, d = threadIdx.x;  // 64 threads
    __shared__ float e[DDIM];
    e[d] = g_e1[i * DDIM + d];
    __syncthreads();
    float s = 0.f;
#pragma unroll 4
    for (int k = 0; k < DDIM; k++) s += e[k] * W2[d * DDIM + k];
    g_fm[i * DDIM + d] = s;
}

// logits[i,n] = sum_k f[i,k]*e3[n,k]
__global__ __launch_bounds__(256) void k_logits() {
    __shared__ float Fs[64][65];
    __shared__ float Es[64][65];
    int bm = blockIdx.y * 64, bn = blockIdx.x * 64;
    int t = threadIdx.x;
    for (int idx = t; idx < 64 * 64; idx += 256) {
        int r = idx >> 6, c = idx & 63;
        Fs[r][c] = g_fm[(bm + r) * 64 + c];
        Es[r][c] = g_e3[(bn + r) * 64 + c];
    }
    __syncthreads();
    int tx = t & 15, ty = t >> 4;
    float acc[4][4] = {};
    for (int k = 0; k < 64; k++) {
        float a[4], b[4];
#pragma unroll
        for (int r = 0; r < 4; r++) { a[r] = Fs[ty * 4 + r][k]; b[r] = Es[tx * 4 + r][k]; }
#pragma unroll
        for (int i = 0; i < 4; i++)
#pragma unroll
            for (int j = 0; j < 4; j++) acc[i][j] += a[i] * b[j];
    }
#pragma unroll
    for (int i = 0; i < 4; i++)
#pragma unroll
        for (int j = 0; j < 4; j++)
            g_attn[(size_t)(bm + ty * 4 + i) * NP + bn + tx * 4 + j] = acc[i][j];
}

// ---------------- fused softmax + top-p (bit-pattern bisection) + mask ----------------
__device__ __forceinline__ float blkSum(float v, float* red) {
#pragma unroll
    for (int o = 16; o; o >>= 1) v += __shfl_xor_sync(0xffffffffu, v, o);
    int warp = threadIdx.x >> 5, lane = threadIdx.x & 31;
    __syncthreads();
    if (lane == 0) red[warp] = v;
    __syncthreads();
    if (threadIdx.x == 0) {
        float s = 0.f;
#pragma unroll
        for (int i = 0; i < 8; i++) s += red[i];
        red[0] = s;
    }
    __syncthreads();
    return red[0];
}

__global__ __launch_bounds__(256) void k_softtopp() {
    __shared__ float red[8];
    int row = blockIdx.x, t = threadIdx.x;
    const float* a = g_attn + (size_t)row * NP;
    float v[8];
#pragma unroll
    for (int u = 0; u < 8; u++) v[u] = a[t + u * 256];
    float m = v[0];
#pragma unroll
    for (int u = 1; u < 8; u++) m = fmaxf(m, v[u]);
#pragma unroll
    for (int o = 16; o; o >>= 1) m = fmaxf(m, __shfl_xor_sync(0xffffffffu, m, o));
    {
        int warp = t >> 5, lane = t & 31;
        if (lane == 0) red[warp] = m;
        __syncthreads();
        if (t == 0) {
            float mm = red[0];
#pragma unroll
            for (int i = 1; i < 8; i++) mm = fmaxf(mm, red[i]);
            red[0] = mm;
        }
        __syncthreads();
        m = red[0];
    }
    float e[8];
    float tot = 0.f;
#pragma unroll
    for (int u = 0; u < 8; u++) { e[u] = __expf(v[u] - m); tot += e[u]; }
    tot = blkSum(tot, red);
    float target = P_TOPP * tot;
    unsigned lo = 0u, hi = 0x3F800000u;
    while (lo < hi) {
        unsigned mid = lo + ((hi - lo + 1) >> 1);
        float tm = __uint_as_float(mid);
        float p = 0.f;
#pragma unroll
        for (int u = 0; u < 8; u++) p += (e[u] >= tm) ? e[u] : 0.f;
        p = blkSum(p, red);
        if (p >= target) lo = mid; else hi = mid - 1;
    }
    float thr = __uint_as_float(lo);
    float F = 0.f;
#pragma unroll
    for (int u = 0; u < 8; u++) F += (e[u] >= thr) ? e[u] : 0.f;
    F = blkSum(F, red);
    float inv = 1.0f / fmaxf(F, 1e-30f);
    bf16* o = g_attnB + (size_t)row * NP;
#pragma unroll
    for (int u = 0; u < 8; u++)
        o[t + u * 256] = __float2bfloat16((e[u] >= thr) ? e[u] * inv : 0.0f);
}

// ---------------- bf16 tensor-core GEMM, ldmatrix fragments ----------------
#define CP_ASYNC16(dst_u32, src_ptr) \
    asm volatile("cp.async.cg.shared.global [%0], [%1], 16;\n" :: "r"(dst_u32), "l"(src_ptr))
#define MMA16816(d, a, b) \
    asm volatile("mma.sync.aligned.m16n8k16.row.col.f32.bf16.bf16.f32 " \
                 "{%0,%1,%2,%3},{%4,%5,%6,%7},{%8,%9},{%0,%1,%2,%3};" \
                 : "+f"(d[0]), "+f"(d[1]), "+f"(d[2]), "+f"(d[3]) \
                 : "r"(a[0]), "r"(a[1]), "r"(a[2]), "r"(a[3]), "r"(b[0]), "r"(b[1]))
#define LDSM_X4(r0, r1, r2, r3, addr) \
    asm volatile("ldmatrix.sync.aligned.m8n8.x4.shared.b16 {%0,%1,%2,%3}, [%4];" \
                 : "=r"(r0), "=r"(r1), "=r"(r2), "=r"(r3) : "r"(addr))

// Two GEMMs in one launch (blockIdx.z selects operand set):
// C[m,n] = sum_k A[m,k]*BT[n,k]; A [M][K], BT [N][K], C [M][N], bf16 row-major.
__global__ __launch_bounds__(256) void k_gemm_bf16_dual(
    const bf16* __restrict__ A0, const bf16* __restrict__ BT0, bf16* __restrict__ C0,
    const bf16* __restrict__ A1, const bf16* __restrict__ BT1, bf16* __restrict__ C1,
    int M, int N, int K)
{
    const bf16* A  = blockIdx.z ? A1  : A0;
    const bf16* BT = blockIdx.z ? BT1 : BT0;
    bf16*       C  = blockIdx.z ? C1  : C0;

    __shared__ uint32_t As[2][128 * 20];
    __shared__ uint32_t Bs[2][128 * 20];
    int t = threadIdx.x;
    int bm = blockIdx.y << 7, bn = blockIdx.x << 7;
    int warp = t >> 5, lane = t & 31;
    int wm = warp & 3, wn = warp >> 2;
    int g = lane >> 2, tq = lane & 3;

    // loader: each thread owns rows (t>>2), (t>>2)+64; 16B chunk (t&3)
    int lrow = t >> 2, lchunk = t & 3;
    const bf16* gA0 = A  + (size_t)(bm + lrow) * K      + lchunk * 8;
    const bf16* gA1 = A  + (size_t)(bm + lrow + 64) * K + lchunk * 8;
    const bf16* gB0 = BT + (size_t)(bn + lrow) * K      + lchunk * 8;
    const bf16* gB1 = BT + (size_t)(bn + lrow + 64) * K + lchunk * 8;
    uint32_t sA0[2], sA1[2], sB0[2], sB1[2];
#pragma unroll
    for (int b = 0; b < 2; b++) {
        sA0[b] = (uint32_t)__cvta_generic_to_shared(&As[b][lrow * 20 + lchunk * 4]);
        sA1[b] = (uint32_t)__cvta_generic_to_shared(&As[b][(lrow + 64) * 20 + lchunk * 4]);
        sB0[b] = (uint32_t)__cvta_generic_to_shared(&Bs[b][lrow * 20 + lchunk * 4]);
        sB1[b] = (uint32_t)__cvta_generic_to_shared(&Bs[b][(lrow + 64) * 20 + lchunk * 4]);
    }
    // ldmatrix base addresses (lane-dependent): row base + (lane&15), chunk bit (lane>>4)
    uint32_t aFragBase[2], bFragBase[2];
#pragma unroll
    for (int b = 0; b < 2; b++) {
        aFragBase[b] = (uint32_t)__cvta_generic_to_shared(
            &As[b][(wm * 32 + (lane & 15)) * 20 + (lane >> 4) * 4]);
        bFragBase[b] = (uint32_t)__cvta_generic_to_shared(
            &Bs[b][(wn * 64 + (lane & 15)) * 20 + (lane >> 4) * 4]);
    }

    float acc[2][8][4] = {};

    int NT = K >> 5;
    CP_ASYNC16(sA0[0], gA0);
    CP_ASYNC16(sA1[0], gA1);
    CP_ASYNC16(sB0[0], gB0);
    CP_ASYNC16(sB1[0], gB1);
    asm volatile("cp.async.commit_group;\n" ::: "memory");

    for (int it = 0; it < NT; it++) {
        int buf = it & 1;
        if (it + 1 < NT) {
            size_t ko = (size_t)(it + 1) << 5;
            CP_ASYNC16(sA0[buf ^ 1], gA0 + ko);
            CP_ASYNC16(sA1[buf ^ 1], gA1 + ko);
            CP_ASYNC16(sB0[buf ^ 1], gB0 + ko);
            CP_ASYNC16(sB1[buf ^ 1], gB1 + ko);
            asm volatile("cp.async.commit_group;\n" ::: "memory");
            asm volatile("cp.async.wait_group 1;\n" ::: "memory");
        } else {
            asm volatile("cp.async.wait_group 0;\n" ::: "memory");
        }
        __syncthreads();

#pragma unroll
        for (int s = 0; s < 2; s++) {
            uint32_t a[2][4], b[8][2];
#pragma unroll
            for (int mi = 0; mi < 2; mi++) {
                uint32_t ad = aFragBase[buf] + ((mi * 16 * 20 + s * 8) << 2);
                LDSM_X4(a[mi][0], a[mi][1], a[mi][2], a[mi][3], ad);
            }
#pragma unroll
            for (int p = 0; p < 4; p++) {
                uint32_t bd = bFragBase[buf] + ((p * 16 * 20 + s * 8) << 2);
                uint32_t r0, r1, r2, r3;
                LDSM_X4(r0, r1, r2, r3, bd);
                b[2 * p][0] = r0; b[2 * p + 1][0] = r1;
                b[2 * p][1] = r2; b[2 * p + 1][1] = r3;
            }
#pragma unroll
            for (int mi = 0; mi < 2; mi++)
#pragma unroll
                for (int ni = 0; ni < 8; ni++)
                    MMA16816(acc[mi][ni], a[mi], b[ni]);
        }
        __syncthreads();
    }

#pragma unroll
    for (int mi = 0; mi < 2; mi++) {
#pragma unroll
        for (int ni = 0; ni < 8; ni++) {
            int row = bm + wm * 32 + mi * 16 + g;
            int col = bn + wn * 64 + ni * 8 + tq * 2;
            __nv_bfloat162* p0 = (__nv_bfloat162*)&C[(size_t)row * N + col];
            __nv_bfloat162* p1 = (__nv_bfloat162*)&C[(size_t)(row + 8) * N + col];
            *p0 = __float22bfloat162_rn(make_float2(acc[mi][ni][0], acc[mi][ni][1]));
            *p1 = __float22bfloat162_rn(make_float2(acc[mi][ni][2], acc[mi][ni][3]));
        }
    }
}

// ---------------- tensor-core delta: res (+)= Xf@Pw^T + Xa@Aw^T, fp32 accum ----------
__global__ __launch_bounds__(256) void k_delta_mma(
    const bf16* __restrict__ Xf, const bf16* __restrict__ Xa,
    const float* __restrict__ Pw, const float* __restrict__ Aw,
    float* __restrict__ R, int accumulate)
{
    extern __shared__ uint32_t sm[];
    uint32_t* sPw = sm;
    uint32_t* sAw = sm + 10240;
    uint32_t* sXf = sm + 20480;
    uint32_t* sXa = sm + 30720;
    int t = threadIdx.x;
    size_t r0 = (size_t)blockIdx.x * 128;

    for (int idx = t; idx < 128 * 64; idx += 256) {
        int n = idx >> 6, w = idx & 63;
        int c = w >> 4, ww = w & 15;
        float2 pv = *(const float2*)&Pw[n * 128 + w * 2];
        float2 av = *(const float2*)&Aw[n * 128 + w * 2];
        __nv_bfloat162 pb = __float22bfloat162_rn(pv);
        __nv_bfloat162 ab = __float22bfloat162_rn(av);
        sPw[c * 2560 + n * 20 + ww] = *(uint32_t*)&pb;
        sAw[c * 2560 + n * 20 + ww] = *(uint32_t*)&ab;
    }
    const uint32_t* xf32 = (const uint32_t*)(Xf + r0 * 128);
    const uint32_t* xa32 = (const uint32_t*)(Xa + r0 * 128);
    for (int idx = t; idx < 128 * 64; idx += 256) {
        int n = idx >> 6, w = idx & 63;
        int c = w >> 4, ww = w & 15;
        sXf[c * 2560 + n * 20 + ww] = xf32[n * 64 + w];
        sXa[c * 2560 + n * 20 + ww] = xa32[n * 64 + w];
    }
    __syncthreads();

    int warp = t >> 5, lane = t & 31;
    int wm = warp & 3, wn = warp >> 2;
    int g = lane >> 2, tq = lane & 3;
    float acc[2][8][4] = {};

#pragma unroll
    for (int c = 0; c < 4; c++) {
        const uint32_t* cf = sXf + c * 2560;
        const uint32_t* ca = sXa + c * 2560;
        const uint32_t* cp = sPw + c * 2560;
        const uint32_t* cw = sAw + c * 2560;
#pragma unroll
        for (int s = 0; s < 2; s++) {
            uint32_t af[2][4], aa[2][4], bp[8][2], ba[8][2];
#pragma unroll
            for (int mi = 0; mi < 2; mi++) {
                int r = (wm * 32 + mi * 16 + g) * 20 + s * 8 + tq;
                af[mi][0] = cf[r];       af[mi][1] = cf[r + 160];
                af[mi][2] = cf[r + 4];   af[mi][3] = cf[r + 164];
                aa[mi][0] = ca[r];       aa[mi][1] = ca[r + 160];
                aa[mi][2] = ca[r + 4];   aa[mi][3] = ca[r + 164];
            }
#pragma unroll
            for (int ni = 0; ni < 8; ni++) {
                int rb = (wn * 64 + ni * 8 + g) * 20 + s * 8 + tq;
                bp[ni][0] = cp[rb]; bp[ni][1] = cp[rb + 4];
                ba[ni][0] = cw[rb]; ba[ni][1] = cw[rb + 4];
            }
#pragma unroll
            for (int mi = 0; mi < 2; mi++)
#pragma unroll
                for (int ni = 0; ni < 8; ni++) {
                    MMA16816(acc[mi][ni], af[mi], bp[ni]);
                    MMA16816(acc[mi][ni], aa[mi], ba[ni]);
                }
        }
    }

#pragma unroll
    for (int mi = 0; mi < 2; mi++) {
#pragma unroll
        for (int ni = 0; ni < 8; ni++) {
            int row = wm * 32 + mi * 16 + g;
            int col = wn * 64 + ni * 8 + tq * 2;
            float* p0 = &R[(r0 + row) * 128 + col];
            float* p1 = &R[(r0 + row + 8) * 128 + col];
            if (accumulate) {
                p0[0] += acc[mi][ni][0]; p0[1] += acc[mi][ni][1];
                p1[0] += acc[mi][ni][2]; p1[1] += acc[mi][ni][3];
            } else {
                *(float2*)p0 = make_float2(acc[mi][ni][0], acc[mi][ni][1]);
                *(float2*)p1 = make_float2(acc[mi][ni][2], acc[mi][ni][3]);
            }
        }
    }
}

// ---------------- final: out = LN(x + sigmoid(alpha)*res) ----------------
__global__ void k_ln(const float* __restrict__ x, const float* __restrict__ gamma,
                     const float* __restrict__ beta, const float* __restrict__ alpha,
                     float* __restrict__ out) {
    int row = blockIdx.x * 8 + (threadIdx.x >> 5);
    int lane = threadIdx.x & 31;
    float gate = 1.0f / (1.0f + expf(-alpha[0]));
    size_t base = (size_t)row * CDIM;
    float h[4];
    float s = 0.f;
#pragma unroll
    for (int u = 0; u < 4; u++) {
        int c = lane + u * 32;
        h[u] = x[base + c] + gate * g_res[base + c];
        s += h[u];
    }
#pragma unroll
    for (int o = 16; o; o >>= 1) s += __shfl_xor_sync(0xffffffffu, s, o);
    float mu = s * (1.0f / CDIM);
    float v = 0.f;
#pragma unroll
    for (int u = 0; u < 4; u++) { float d = h[u] - mu; v += d * d; }
#pragma unroll
    for (int o = 16; o; o >>= 1) v += __shfl_xor_sync(0xffffffffu, v, o);
    float rs = rsqrtf(v * (1.0f / CDIM) + LN_EPS);
#pragma unroll
    for (int u = 0; u < 4; u++) {
        int c = lane + u * 32;
        out[base + c] = (h[u] - mu) * rs * gamma[c] + beta[c];
    }
}

// ---------------- host orchestration ----------------
extern "C" void kernel_launch(void* const* d_in, const int* in_sizes, int n_in,
                              void* d_out, int out_size) {
    const float* x     = (const float*)d_in[0];
    const float* prior = (const float*)d_in[1];
    const float* W1    = (const float*)d_in[2];
    const float* W2    = (const float*)d_in[3];
    const float* W3    = (const float*)d_in[4];
    const float* Pfw   = (const float*)d_in[5];
    const float* Awt   = (const float*)d_in[6];
    const float* gamma = (const float*)d_in[7];
    const float* beta  = (const float*)d_in[8];
    const float* alpha = (const float*)d_in[9];
    float* out = (float*)d_out;

    bf16 *RfB, *attnB, *xT, *Xf1, *Xa1, *Xf2, *Xa2, *Xf1T, *Xa1T;
    float *res;
    cudaGetSymbolAddress((void**)&RfB,   g_RfB);
    cudaGetSymbolAddress((void**)&attnB, g_attnB);
    cudaGetSymbolAddress((void**)&xT,    g_xT);
    cudaGetSymbolAddress((void**)&Xf1,   g_Xf1);
    cudaGetSymbolAddress((void**)&Xa1,   g_Xa1);
    cudaGetSymbolAddress((void**)&Xf2,   g_Xf2);
    cudaGetSymbolAddress((void**)&Xa2,   g_Xa2);
    cudaGetSymbolAddress((void**)&Xf1T,  g_Xf1T);
    cudaGetSymbolAddress((void**)&Xa1T,  g_Xa1T);
    cudaGetSymbolAddress((void**)&res,   g_res);

    static bool attr_done = false;
    if (!attr_done) {
        cudaFuncSetAttribute(k_delta_mma, cudaFuncAttributeMaxDynamicSharedMemorySize, 163840);
        attr_done = true;
    }

    k_rowsum<<<NP, 256>>>(prior);
    k_scaleRf<<<4096, 256>>>(prior);
    k_transpose_f2b<<<dim3(NCC / 32, NP / 32), dim3(32, 8)>>>(x, xT, NP, NCC);

    for (int step = 0; step < 2; step++) {
        if (step == 0) k_pool_f<<<NP, CDIM>>>(x);
        else           k_pool_b<<<NP, CDIM>>>(Xa1);
        k_e1e3<<<NP, DDIM>>>(W1, W3);
        k_f<<<NP, DDIM>>>(W2);
        k_logits<<<dim3(32, 32), 256>>>();
        k_softtopp<<<NP, 256>>>();

        const bf16* BT_f = step ? (const bf16*)Xf1T : (const bf16*)xT;
        const bf16* BT_a = step ? (const bf16*)Xa1T : (const bf16*)xT;
        bf16* Xf_out = step ? Xf2 : Xf1;
        bf16* Xa_out = step ? Xa2 : Xa1;

        k_gemm_bf16_dual<<<dim3(NCC / 128, NP / 128, 2), 256>>>(
            RfB, BT_f, Xf_out, attnB, BT_a, Xa_out, NP, NCC, NP);

        k_delta_mma<<<1024, 256, 163840>>>(Xf_out, Xa_out,
                               Pfw + (size_t)step * CDIM * CDIM,
                               Awt + (size_t)step * CDIM * CDIM,
                               res, step);

        if (step == 0) {
            k_transpose_b2b<<<dim3(NCC / 32, NP / 32), dim3(32, 8)>>>(Xf1, Xf1T, NP, NCC);
            k_transpose_b2b<<<dim3(NCC / 32, NP / 32), dim3(32, 8)>>>(Xa1, Xa1T, NP, NCC);
        }
    }

    k_ln<<<(int)(TOT / CDIM / 8), 256>>>(x, gamma, beta, alpha, out);
}